// round 12
// baseline (speedup 1.0000x reference)
#include <cuda_runtime.h>
#include <cuda_bf16.h>
#include <math.h>
#include <cstdint>

constexpr int NB  = 8;
constexpr int NI  = 2048;
constexpr int DIM = 1024;
constexpr int HD  = 512;
constexpr int DA  = 256;
constexpr int KN  = 5;
constexpr int KC  = 9;            // candidates for exact re-rank
constexpr int NC  = 2;
constexpr int MROWS = NB * NI;    // 16384
constexpr int NTILE = NI / 128;   // 16 col-blocks per bag row

// Scratch (static device globals)
__device__ float d_x [MROWS * HD];
__device__ float d_sq[MROWS];
__device__ float d_pv[(size_t)MROWS * NTILE * KC];   // partial cand values
__device__ int   d_pi[(size_t)MROWS * NTILE * KC];   // partial cand indices
__device__ int   d_cand[MROWS * KC];
__device__ int   d_idx[MROWS * KN];
__device__ float d_P [MROWS * HD];
__device__ float d_Q [MROWS * HD];
__device__ float d_g [MROWS * HD];
__device__ float d_Ap[MROWS * DA];
__device__ float d_Bp[MROWS * DA];
__device__ float d_Ar[MROWS];
__device__ float d_M [NB * HD];

// ===========================================================================
// PART 1: fp32 FFMA GEMM (exact) — fc layer only (kNN-critical x).
// ===========================================================================
constexpr int FBM = 128, FBN = 128, FBK = 8;

__global__ __launch_bounds__(256, 2)
void gemm_f32_relu(const float* __restrict__ A, const float* __restrict__ Bm,
                   const float* __restrict__ bias, float* __restrict__ Cm,
                   int M, int Kd, int Nd) {
    __shared__ float As[2][FBK][FBM];
    __shared__ float Bs[2][FBK][FBN];
    const int tid = threadIdx.x;
    const int tx = tid & 15, ty = tid >> 4;
    const int rowBase = blockIdx.y * FBM;
    const int colBase = blockIdx.x * FBN;
    const int arow = tid >> 1, acol = (tid & 1) * 4;
    const int brow = tid >> 5, bcol = (tid & 31) * 4;

    float4 aR = *(const float4*)(A + (size_t)(rowBase + arow) * Kd + acol);
    float4 bR = *(const float4*)(Bm + (size_t)brow * Nd + colBase + bcol);
    As[0][acol + 0][arow] = aR.x; As[0][acol + 1][arow] = aR.y;
    As[0][acol + 2][arow] = aR.z; As[0][acol + 3][arow] = aR.w;
    *(float4*)&Bs[0][brow][bcol] = bR;
    __syncthreads();

    float acc[8][8];
#pragma unroll
    for (int m = 0; m < 8; m++)
#pragma unroll
        for (int n = 0; n < 8; n++) acc[m][n] = 0.f;

    const int KT = Kd / FBK;
    for (int kt = 0; kt < KT; kt++) {
        const int cur = kt & 1;
        if (kt + 1 < KT) {
            const int k0 = (kt + 1) * FBK;
            aR = *(const float4*)(A + (size_t)(rowBase + arow) * Kd + k0 + acol);
            bR = *(const float4*)(Bm + (size_t)(k0 + brow) * Nd + colBase + bcol);
        }
#pragma unroll
        for (int kk = 0; kk < FBK; kk++) {
            float4 a0 = *(const float4*)&As[cur][kk][ty * 4];
            float4 a1 = *(const float4*)&As[cur][kk][64 + ty * 4];
            float4 b0 = *(const float4*)&Bs[cur][kk][tx * 4];
            float4 b1 = *(const float4*)&Bs[cur][kk][64 + tx * 4];
            float av[8] = {a0.x, a0.y, a0.z, a0.w, a1.x, a1.y, a1.z, a1.w};
            float bv[8] = {b0.x, b0.y, b0.z, b0.w, b1.x, b1.y, b1.z, b1.w};
#pragma unroll
            for (int m = 0; m < 8; m++)
#pragma unroll
                for (int n = 0; n < 8; n++)
                    acc[m][n] = fmaf(av[m], bv[n], acc[m][n]);
        }
        if (kt + 1 < KT) {
            const int nxt = cur ^ 1;
            As[nxt][acol + 0][arow] = aR.x; As[nxt][acol + 1][arow] = aR.y;
            As[nxt][acol + 2][arow] = aR.z; As[nxt][acol + 3][arow] = aR.w;
            *(float4*)&Bs[nxt][brow][bcol] = bR;
            __syncthreads();
        }
    }

#pragma unroll
    for (int m = 0; m < 8; m++) {
        const int r = rowBase + ((m < 4) ? (ty * 4 + m) : (64 + ty * 4 + (m - 4)));
        const int c0 = colBase + tx * 4;
        const int c1 = colBase + 64 + tx * 4;
        float4 t0 = *(const float4*)&bias[c0];
        float4 t1 = *(const float4*)&bias[c1];
        float4 v0, v1;
        v0.x = fmaxf(acc[m][0] + t0.x, 0.f); v0.y = fmaxf(acc[m][1] + t0.y, 0.f);
        v0.z = fmaxf(acc[m][2] + t0.z, 0.f); v0.w = fmaxf(acc[m][3] + t0.w, 0.f);
        v1.x = fmaxf(acc[m][4] + t1.x, 0.f); v1.y = fmaxf(acc[m][5] + t1.y, 0.f);
        v1.z = fmaxf(acc[m][6] + t1.z, 0.f); v1.w = fmaxf(acc[m][7] + t1.w, 0.f);
        *(float4*)&Cm[(size_t)r * Nd + c0] = v0;
        *(float4*)&Cm[(size_t)r * Nd + c1] = v1;
    }
}

// ===========================================================================
// Shared bf16-3x pieces
// ===========================================================================
constexpr int XBM = 128, XBN = 128, XBK = 16;
constexpr int LDW = 136;              // padded u32 row
constexpr int ARR = 8 * LDW;

__device__ __forceinline__ uint32_t pack_hi(float a, float b, float& la, float& lb) {
    __nv_bfloat16 ha = __float2bfloat16_rn(a);
    __nv_bfloat16 hb = __float2bfloat16_rn(b);
    la = a - __bfloat162float(ha);
    lb = b - __bfloat162float(hb);
    return ((uint32_t)__bfloat16_as_ushort(hb) << 16) | __bfloat16_as_ushort(ha);
}
__device__ __forceinline__ uint32_t pack_lo(float la, float lb) {
    __nv_bfloat162 t = __floats2bfloat162_rn(la, lb);
    return *(uint32_t*)&t;
}
__device__ __forceinline__ void mma_bf16(float* c, uint32_t a0, uint32_t a1,
                                         uint32_t a2, uint32_t a3,
                                         uint32_t b0, uint32_t b1) {
    asm volatile(
        "mma.sync.aligned.m16n8k16.row.col.f32.bf16.bf16.f32 "
        "{%0,%1,%2,%3}, {%4,%5,%6,%7}, {%8,%9}, {%0,%1,%2,%3};\n"
        : "+f"(c[0]), "+f"(c[1]), "+f"(c[2]), "+f"(c[3])
        : "r"(a0), "r"(a1), "r"(a2), "r"(a3), "r"(b0), "r"(b1));
}

// ===========================================================================
// PART 2a: bf16-3x GEMM (plain, N-major B) — P/Q/Ap/Bp.
// ===========================================================================
__global__ __launch_bounds__(256, 2)
void gemm_bf(const float* __restrict__ A, const float* __restrict__ B,
             float* __restrict__ C, int M, int Kd, int Nd) {
    const int rowBase = blockIdx.y * XBM, colBase = blockIdx.x * XBN;
    __shared__ uint32_t S[2][4][ARR];

    const int tid = threadIdx.x;
    const int lane = tid & 31;
    const int grp = lane >> 2;
    const int tig = lane & 3;
    const int warpId = tid >> 5;
    const int wm = (warpId & 1) * 64;
    const int wn = (warpId >> 1) * 32;

    const int sa_row = tid >> 3;
    const int sa_k2  = tid & 7;
    const int sb_k2  = tid >> 5;
    const int sb_n   = (tid & 31) * 4;

    float2 pa[4];
    float4 pw0, pw1;

    auto gload = [&](int k0) {
#pragma unroll
        for (int p = 0; p < 4; p++)
            pa[p] = *(const float2*)(A + (size_t)(rowBase + p * 32 + sa_row) * Kd + k0 + sa_k2 * 2);
        const int k = k0 + sb_k2 * 2;
        pw0 = *(const float4*)(B + (size_t)k * Nd + colBase + sb_n);
        pw1 = *(const float4*)(B + (size_t)(k + 1) * Nd + colBase + sb_n);
    };
    auto sstore = [&](int buf) {
#pragma unroll
        for (int p = 0; p < 4; p++) {
            const int row = p * 32 + sa_row;
            float la, lb;
            uint32_t h = pack_hi(pa[p].x, pa[p].y, la, lb);
            S[buf][0][sa_k2 * LDW + row] = h;
            S[buf][1][sa_k2 * LDW + row] = pack_lo(la, lb);
        }
        float l0, l1, l2, l3, l4, l5, l6, l7;
        uint32_t h0 = pack_hi(pw0.x, pw1.x, l0, l1);
        uint32_t h1 = pack_hi(pw0.y, pw1.y, l2, l3);
        uint32_t h2 = pack_hi(pw0.z, pw1.z, l4, l5);
        uint32_t h3 = pack_hi(pw0.w, pw1.w, l6, l7);
        *(uint4*)&S[buf][2][sb_k2 * LDW + sb_n] = make_uint4(h0, h1, h2, h3);
        *(uint4*)&S[buf][3][sb_k2 * LDW + sb_n] =
            make_uint4(pack_lo(l0, l1), pack_lo(l2, l3), pack_lo(l4, l5), pack_lo(l6, l7));
    };

    gload(0);
    sstore(0);
    __syncthreads();

    float acc[4][4][4];
#pragma unroll
    for (int mi = 0; mi < 4; mi++)
#pragma unroll
        for (int ni = 0; ni < 4; ni++)
#pragma unroll
            for (int q = 0; q < 4; q++) acc[mi][ni][q] = 0.f;

    const int KT = Kd / XBK;
    for (int kt = 0; kt < KT; kt++) {
        const int cur = kt & 1;
        if (kt + 1 < KT) gload((kt + 1) * XBK);

        uint32_t bhi[4][2], blo[4][2];
#pragma unroll
        for (int ni = 0; ni < 4; ni++) {
            const int n = wn + ni * 8 + grp;
            bhi[ni][0] = S[cur][2][tig * LDW + n];
            bhi[ni][1] = S[cur][2][(tig + 4) * LDW + n];
            blo[ni][0] = S[cur][3][tig * LDW + n];
            blo[ni][1] = S[cur][3][(tig + 4) * LDW + n];
        }
#pragma unroll
        for (int mi = 0; mi < 4; mi++) {
            const int r = wm + mi * 16 + grp;
            uint32_t ah0 = S[cur][0][tig * LDW + r];
            uint32_t ah1 = S[cur][0][tig * LDW + r + 8];
            uint32_t ah2 = S[cur][0][(tig + 4) * LDW + r];
            uint32_t ah3 = S[cur][0][(tig + 4) * LDW + r + 8];
            uint32_t al0 = S[cur][1][tig * LDW + r];
            uint32_t al1 = S[cur][1][tig * LDW + r + 8];
            uint32_t al2 = S[cur][1][(tig + 4) * LDW + r];
            uint32_t al3 = S[cur][1][(tig + 4) * LDW + r + 8];
#pragma unroll
            for (int ni = 0; ni < 4; ni++) {
                mma_bf16(acc[mi][ni], ah0, ah1, ah2, ah3, bhi[ni][0], bhi[ni][1]);
                mma_bf16(acc[mi][ni], ah0, ah1, ah2, ah3, blo[ni][0], blo[ni][1]);
                mma_bf16(acc[mi][ni], al0, al1, al2, al3, bhi[ni][0], bhi[ni][1]);
            }
        }
        if (kt + 1 < KT) {
            sstore(cur ^ 1);
            __syncthreads();
        }
    }

#pragma unroll
    for (int mi = 0; mi < 4; mi++) {
        const int row = rowBase + wm + mi * 16 + grp;
#pragma unroll
        for (int ni = 0; ni < 4; ni++) {
            const int col = colBase + wn + ni * 8 + tig * 2;
            float2 v0; v0.x = acc[mi][ni][0]; v0.y = acc[mi][ni][1];
            float2 v1; v1.x = acc[mi][ni][2]; v1.y = acc[mi][ni][3];
            *(float2*)&C[(size_t)row * Nd + col] = v0;
            *(float2*)&C[(size_t)(row + 8) * Nd + col] = v1;
        }
    }
}

// ===========================================================================
// PART 2b: fused Gram(bf16-3x) + in-tile top-KC selection.
// Tile (by,bx), by<=bx. d2 tile kept in dynamic smem (128x129 f32);
// per-row top-KC of the tile's 128 cols (pass A) and — via symmetry —
// per-col top-KC down rows (pass B, bx!=by) written to d_pv/d_pi.
// ===========================================================================
constexpr int TILE_STRIDE = 129;
constexpr int GRAM_DSMEM = 128 * TILE_STRIDE * 4;   // 66048 B

__device__ __forceinline__ void tile_select(const float* tileD, int trans,
                                            int rowBase, int colBase, int slot,
                                            int bag, int warpId, int lane) {
    for (int rr = 0; rr < 16; rr++) {
        const int r = warpId * 16 + rr;
        float v[4]; int ix[4];
#pragma unroll
        for (int t = 0; t < 4; t++) {
            const int c = t * 32 + lane;
            v[t] = trans ? tileD[c * TILE_STRIDE + r] : tileD[r * TILE_STRIDE + c];
            ix[t] = (trans ? rowBase : colBase) + c;
        }
        // sort4 ascending by (val, idx)
#define CSW(a, b) { if (v[b] < v[a] || (v[b] == v[a] && ix[b] < ix[a])) { \
        float tv = v[a]; v[a] = v[b]; v[b] = tv; int ti = ix[a]; ix[a] = ix[b]; ix[b] = ti; } }
        CSW(0, 1) CSW(2, 3) CSW(0, 2) CSW(1, 3) CSW(1, 2)
#undef CSW
        const int grow = bag * NI + (trans ? colBase : rowBase) + r;
        float* opv = d_pv + ((size_t)grow * NTILE + slot) * KC;
        int*   opi = d_pi + ((size_t)grow * NTILE + slot) * KC;
        int ptr = 0;
        float cv = v[0]; int ci = ix[0];
#pragma unroll
        for (int k = 0; k < KC; k++) {
            float rv = cv; int ri = ci;
#pragma unroll
            for (int off = 16; off > 0; off >>= 1) {
                float ov = __shfl_xor_sync(0xffffffffu, rv, off);
                int   oj = __shfl_xor_sync(0xffffffffu, ri, off);
                if (ov < rv || (ov == rv && oj < ri)) { rv = ov; ri = oj; }
            }
            if (lane == 0) { opv[k] = rv; opi[k] = ri; }
            if (cv == rv && ci == ri) {
                ptr++;
                float nv = 3.4e38f; int nj = 0x7fffffff;
                if (ptr == 1) { nv = v[1]; nj = ix[1]; }
                else if (ptr == 2) { nv = v[2]; nj = ix[2]; }
                else if (ptr == 3) { nv = v[3]; nj = ix[3]; }
                cv = nv; ci = nj;
            }
        }
    }
}

__global__ __launch_bounds__(256, 2)
void gram_topk(const float* __restrict__ xall) {
    const int bx = blockIdx.x, by = blockIdx.y;
    if (by > bx) return;
    const int bag = blockIdx.z;
    const float* A = xall + (size_t)bag * NI * HD;
    const float* sqb = d_sq + bag * NI;
    const int rowBase = by * XBM, colBase = bx * XBN;

    __shared__ uint32_t S[2][4][ARR];
    extern __shared__ float tileD[];

    const int tid = threadIdx.x;
    const int lane = tid & 31;
    const int grp = lane >> 2;
    const int tig = lane & 3;
    const int warpId = tid >> 5;
    const int wm = (warpId & 1) * 64;
    const int wn = (warpId >> 1) * 32;

    const int sa_row = tid >> 3;
    const int sa_k2  = tid & 7;

    float2 pa[4], pb[4];

    auto gload = [&](int k0) {
#pragma unroll
        for (int p = 0; p < 4; p++) {
            pa[p] = *(const float2*)(A + (size_t)(rowBase + p * 32 + sa_row) * HD + k0 + sa_k2 * 2);
            pb[p] = *(const float2*)(A + (size_t)(colBase + p * 32 + sa_row) * HD + k0 + sa_k2 * 2);
        }
    };
    auto sstore = [&](int buf) {
#pragma unroll
        for (int p = 0; p < 4; p++) {
            const int row = p * 32 + sa_row;
            float la, lb;
            uint32_t h = pack_hi(pa[p].x, pa[p].y, la, lb);
            S[buf][0][sa_k2 * LDW + row] = h;
            S[buf][1][sa_k2 * LDW + row] = pack_lo(la, lb);
            uint32_t h2 = pack_hi(pb[p].x, pb[p].y, la, lb);
            S[buf][2][sa_k2 * LDW + row] = h2;
            S[buf][3][sa_k2 * LDW + row] = pack_lo(la, lb);
        }
    };

    gload(0);
    sstore(0);
    __syncthreads();

    float acc[4][4][4];
#pragma unroll
    for (int mi = 0; mi < 4; mi++)
#pragma unroll
        for (int ni = 0; ni < 4; ni++)
#pragma unroll
            for (int q = 0; q < 4; q++) acc[mi][ni][q] = 0.f;

    const int KT = HD / XBK;
    for (int kt = 0; kt < KT; kt++) {
        const int cur = kt & 1;
        if (kt + 1 < KT) gload((kt + 1) * XBK);

        uint32_t bhi[4][2], blo[4][2];
#pragma unroll
        for (int ni = 0; ni < 4; ni++) {
            const int n = wn + ni * 8 + grp;
            bhi[ni][0] = S[cur][2][tig * LDW + n];
            bhi[ni][1] = S[cur][2][(tig + 4) * LDW + n];
            blo[ni][0] = S[cur][3][tig * LDW + n];
            blo[ni][1] = S[cur][3][(tig + 4) * LDW + n];
        }
#pragma unroll
        for (int mi = 0; mi < 4; mi++) {
            const int r = wm + mi * 16 + grp;
            uint32_t ah0 = S[cur][0][tig * LDW + r];
            uint32_t ah1 = S[cur][0][tig * LDW + r + 8];
            uint32_t ah2 = S[cur][0][(tig + 4) * LDW + r];
            uint32_t ah3 = S[cur][0][(tig + 4) * LDW + r + 8];
            uint32_t al0 = S[cur][1][tig * LDW + r];
            uint32_t al1 = S[cur][1][tig * LDW + r + 8];
            uint32_t al2 = S[cur][1][(tig + 4) * LDW + r];
            uint32_t al3 = S[cur][1][(tig + 4) * LDW + r + 8];
#pragma unroll
            for (int ni = 0; ni < 4; ni++) {
                mma_bf16(acc[mi][ni], ah0, ah1, ah2, ah3, bhi[ni][0], bhi[ni][1]);
                mma_bf16(acc[mi][ni], ah0, ah1, ah2, ah3, blo[ni][0], blo[ni][1]);
                mma_bf16(acc[mi][ni], al0, al1, al2, al3, bhi[ni][0], bhi[ni][1]);
            }
        }
        if (kt + 1 < KT) {
            sstore(cur ^ 1);
            __syncthreads();
        }
    }

    // d2 tile -> smem
    __syncthreads();
#pragma unroll
    for (int mi = 0; mi < 4; mi++) {
        const int r0 = wm + mi * 16 + grp;
        const float sr0 = sqb[rowBase + r0], sr8 = sqb[rowBase + r0 + 8];
#pragma unroll
        for (int ni = 0; ni < 4; ni++) {
            const int c = wn + ni * 8 + tig * 2;
            const float sc0 = sqb[colBase + c], sc1 = sqb[colBase + c + 1];
            tileD[r0 * TILE_STRIDE + c]           = sr0 + sc0 - 2.f * acc[mi][ni][0];
            tileD[r0 * TILE_STRIDE + c + 1]       = sr0 + sc1 - 2.f * acc[mi][ni][1];
            tileD[(r0 + 8) * TILE_STRIDE + c]     = sr8 + sc0 - 2.f * acc[mi][ni][2];
            tileD[(r0 + 8) * TILE_STRIDE + c + 1] = sr8 + sc1 - 2.f * acc[mi][ni][3];
        }
    }
    __syncthreads();

    tile_select(tileD, 0, rowBase, colBase, bx, bag, warpId, lane);
    if (bx != by)
        tile_select(tileD, 1, rowBase, colBase, by, bag, warpId, lane);
}

// ---------------------------------------------------------------------------
// Merge 16xKC partial candidates -> global approx top-KC. Warp per row.
// ---------------------------------------------------------------------------
__global__ void merge_cand_kernel() {
    const int w = threadIdx.x >> 5;
    const int lane = threadIdx.x & 31;
    const int row = blockIdx.x * 4 + w;
    const float* pv = d_pv + (size_t)row * NTILE * KC;
    const int*   pi = d_pi + (size_t)row * NTILE * KC;

    float bd[KC]; int bix[KC];
#pragma unroll
    for (int k = 0; k < KC; k++) { bd[k] = 3.4e38f; bix[k] = 0x7fffffff; }

    for (int j = lane; j < NTILE * KC; j += 32) {
        float v = pv[j]; int ii = pi[j];
        if (v < bd[KC - 1] || (v == bd[KC - 1] && ii < bix[KC - 1])) {
            bd[KC - 1] = v; bix[KC - 1] = ii;
#pragma unroll
            for (int q = KC - 1; q > 0; q--) {
                if (bd[q] < bd[q - 1] || (bd[q] == bd[q - 1] && bix[q] < bix[q - 1])) {
                    float tf = bd[q]; bd[q] = bd[q - 1]; bd[q - 1] = tf;
                    int ti = bix[q]; bix[q] = bix[q - 1]; bix[q - 1] = ti;
                }
            }
        }
    }

    int* oc = d_cand + (size_t)row * KC;
    int cp = 0;
    float cv = bd[0]; int ci = bix[0];
#pragma unroll
    for (int k = 0; k < KC; k++) {
        float rv = cv; int ri = ci;
#pragma unroll
        for (int off = 16; off > 0; off >>= 1) {
            float ov = __shfl_xor_sync(0xffffffffu, rv, off);
            int   oj = __shfl_xor_sync(0xffffffffu, ri, off);
            if (ov < rv || (ov == rv && oj < ri)) { rv = ov; ri = oj; }
        }
        if (lane == 0) oc[k] = ri;
        if (cv == rv && ci == ri) {
            cp++;
            float nv = 3.4e38f; int ni2 = 0x7fffffff;
#pragma unroll
            for (int q = 1; q < KC; q++) if (cp == q) { nv = bd[q]; ni2 = bix[q]; }
            cv = nv; ci = ni2;
        }
    }
}

// ---------------------------------------------------------------------------
// Row squared norms
// ---------------------------------------------------------------------------
__global__ void sqnorm_kernel() {
    const int row = blockIdx.x, tid = threadIdx.x;
    __shared__ float sh[4];
    const float* xr = d_x + (size_t)row * HD;
    float4 v = *(const float4*)(xr + tid * 4);
    float s = v.x * v.x + v.y * v.y + v.z * v.z + v.w * v.w;
    const int lane = tid & 31, w = tid >> 5;
#pragma unroll
    for (int o = 16; o > 0; o >>= 1) s += __shfl_down_sync(0xffffffffu, s, o);
    if (lane == 0) sh[w] = s;
    __syncthreads();
    if (tid == 0) d_sq[row] = sh[0] + sh[1] + sh[2] + sh[3];
}

// ---------------------------------------------------------------------------
// Exact fp32 re-rank of KC candidates -> true top-KN.
// ---------------------------------------------------------------------------
__global__ void rerank_kernel() {
    const int row = blockIdx.x;
    const int b = row >> 11;
    const int wid = threadIdx.x >> 5, lane = threadIdx.x & 31;
    __shared__ float sval[KC];
    __shared__ int   sidx[KC];

    if (wid < KC) {
        const int j = d_cand[(size_t)row * KC + wid];
        const float* xi = d_x + (size_t)row * HD;
        const float* xj = d_x + (size_t)(b * NI + j) * HD;
        float acc = 0.f;
#pragma unroll
        for (int t = 0; t < 4; t++) {
            float4 a = *(const float4*)(xi + (lane + t * 32) * 4);
            float4 c = *(const float4*)(xj + (lane + t * 32) * 4);
            acc += a.x * c.x + a.y * c.y + a.z * c.z + a.w * c.w;
        }
#pragma unroll
        for (int o = 16; o > 0; o >>= 1) acc += __shfl_down_sync(0xffffffffu, acc, o);
        if (lane == 0) {
            sval[wid] = d_sq[b * NI + j] - 2.f * acc;
            sidx[wid] = j;
        }
    }
    __syncthreads();
    if (threadIdx.x == 0) {
        int* oi = d_idx + (size_t)row * KN;
        bool used[KC];
#pragma unroll
        for (int k = 0; k < KC; k++) used[k] = false;
#pragma unroll
        for (int k = 0; k < KN; k++) {
            float best = 3.5e38f; int bi = 0x7fffffff; int bp = 0;
#pragma unroll
            for (int t = 0; t < KC; t++) {
                if (!used[t]) {
                    float v = sval[t]; int ii = sidx[t];
                    if (v < best || (v == best && ii < bi)) { best = v; bi = ii; bp = t; }
                }
            }
            used[bp] = true;
            oi[k] = bi;
        }
    }
}

// ---------------------------------------------------------------------------
// EdgeConv: g[row,h] = max_k relu(P - Q + b_g + Q[nbr_k])
// ---------------------------------------------------------------------------
__global__ void edgeconv_kernel(const float* __restrict__ bgv) {
    const int row = blockIdx.x;
    const int b = row >> 11;
    const int tid = threadIdx.x;
    __shared__ int sj[KN];
    if (tid < KN) sj[tid] = d_idx[(size_t)row * KN + tid];
    __syncthreads();
    const int hh = tid * 4;
    float4 p  = *(const float4*)(d_P + (size_t)row * HD + hh);
    float4 q  = *(const float4*)(d_Q + (size_t)row * HD + hh);
    float4 bg = *(const float4*)(bgv + hh);
    float bx_ = p.x - q.x + bg.x;
    float by_ = p.y - q.y + bg.y;
    float bz_ = p.z - q.z + bg.z;
    float bw_ = p.w - q.w + bg.w;
    float mx = 0.f, my = 0.f, mz = 0.f, mw = 0.f;
    const float* Qb = d_Q + (size_t)b * NI * HD;
#pragma unroll
    for (int k = 0; k < KN; k++) {
        float4 qk = *(const float4*)(Qb + (size_t)sj[k] * HD + hh);
        mx = fmaxf(mx, bx_ + qk.x);
        my = fmaxf(my, by_ + qk.y);
        mz = fmaxf(mz, bz_ + qk.z);
        mw = fmaxf(mw, bw_ + qk.w);
    }
    float4 o; o.x = mx; o.y = my; o.z = mz; o.w = mw;
    *(float4*)(d_g + (size_t)row * HD + hh) = o;
}

__device__ __forceinline__ float blockReduceSum(float v, float* sh) {
    int lane = threadIdx.x & 31, w = threadIdx.x >> 5;
#pragma unroll
    for (int o = 16; o > 0; o >>= 1) v += __shfl_down_sync(0xffffffffu, v, o);
    if (lane == 0) sh[w] = v;
    __syncthreads();
    int nw = blockDim.x >> 5;
    v = (threadIdx.x < nw) ? sh[threadIdx.x] : 0.f;
    if (w == 0)
#pragma unroll
        for (int o = 16; o > 0; o >>= 1) v += __shfl_down_sync(0xffffffffu, v, o);
    return v;
}

// ---------------------------------------------------------------------------
// Gated attention score -> A_raw
// ---------------------------------------------------------------------------
__global__ void gate_kernel(const float* __restrict__ ba, const float* __restrict__ bb,
                            const float* __restrict__ Wc, const float* __restrict__ bc,
                            float* __restrict__ out) {
    const int row = blockIdx.x, tid = threadIdx.x;
    __shared__ float sh[32];
    const float* ap = d_Ap + (size_t)row * DA;
    const float* bp = d_Bp + (size_t)row * DA;
    float s = 0.f;
    for (int dd = tid; dd < DA; dd += 128) {
        float av = tanhf(ap[dd] + ba[dd]);
        float bv = bp[dd] + bb[dd];
        bv = 1.f / (1.f + expf(-bv));
        s += av * bv * Wc[dd];
    }
    s = blockReduceSum(s, sh);
    if (tid == 0) {
        float v = s + bc[0];
        d_Ar[row] = v;
        out[2 * NB * NC + row] = v;
    }
}

// ---------------------------------------------------------------------------
// Per-bag softmax stats; zero d_M.
// ---------------------------------------------------------------------------
__global__ void attn_stats_kernel() {
    const int b = blockIdx.x, tid = threadIdx.x;
    __shared__ float red[512];
    float* Ar = d_Ar + (size_t)b * NI;

    float mx = -3.4e38f;
    for (int n = tid; n < NI; n += 512) mx = fmaxf(mx, Ar[n]);
    red[tid] = mx; __syncthreads();
    for (int s = 256; s > 0; s >>= 1) { if (tid < s) red[tid] = fmaxf(red[tid], red[tid + s]); __syncthreads(); }
    mx = red[0];
    __syncthreads();

    float sum = 0.f;
    for (int n = tid; n < NI; n += 512) sum += expf(Ar[n] - mx);
    red[tid] = sum; __syncthreads();
    for (int s = 256; s > 0; s >>= 1) { if (tid < s) red[tid] += red[tid + s]; __syncthreads(); }
    const float inv = 1.f / red[0];
    __syncthreads();

    for (int n = tid; n < NI; n += 512) Ar[n] = expf(Ar[n] - mx) * inv;
    d_M[b * HD + tid] = 0.f;
}

// ---------------------------------------------------------------------------
// Chunked weighted pooling with atomics
// ---------------------------------------------------------------------------
__global__ void pool_acc_kernel() {
    const int b = blockIdx.x, ch = blockIdx.y, tid = threadIdx.x;
    const float* w  = d_Ar + (size_t)b * NI + ch * 128;
    const float* gb = d_g + ((size_t)b * NI + (size_t)ch * 128) * HD;
    __shared__ float ws[128];
    if (tid < 128) ws[tid] = w[tid];
    __syncthreads();
    const int c0 = tid, c1 = tid + 256;
    float a0 = 0.f, a1 = 0.f;
    for (int n = 0; n < 128; n++) {
        const float wn = ws[n];
        a0 = fmaf(wn, gb[(size_t)n * HD + c0], a0);
        a1 = fmaf(wn, gb[(size_t)n * HD + c1], a1);
    }
    atomicAdd(&d_M[b * HD + c0], a0);
    atomicAdd(&d_M[b * HD + c1], a1);
}

// ---------------------------------------------------------------------------
// Classifier head + Y_prob
// ---------------------------------------------------------------------------
__global__ void head_kernel(const float* __restrict__ Wcls, const float* __restrict__ bcls,
                            float* __restrict__ out) {
    const int b = blockIdx.x, tid = threadIdx.x;
    __shared__ float sh[32];
    float s0 = 0.f, s1 = 0.f;
    for (int hh = tid; hh < HD; hh += 128) {
        float m = d_M[b * HD + hh];
        s0 = fmaf(m, Wcls[hh * NC + 0], s0);
        s1 = fmaf(m, Wcls[hh * NC + 1], s1);
    }
    s0 = blockReduceSum(s0, sh);
    __syncthreads();
    s1 = blockReduceSum(s1, sh);
    if (tid == 0) {
        float l0 = s0 + bcls[0], l1 = s1 + bcls[1];
        out[b * NC + 0] = l0;
        out[b * NC + 1] = l1;
        float mx = fmaxf(l0, l1);
        float e0 = expf(l0 - mx), e1 = expf(l1 - mx);
        float inv = 1.f / (e0 + e1);
        out[NB * NC + b * NC + 0] = e0 * inv;
        out[NB * NC + b * NC + 1] = e1 * inv;
    }
}

// ---------------------------------------------------------------------------
extern "C" void kernel_launch(void* const* d_in, const int* in_sizes, int n_in,
                              void* d_out, int out_size) {
    const float* h     = (const float*)d_in[0];
    const float* W_fc  = (const float*)d_in[1];
    const float* b_fc  = (const float*)d_in[2];
    const float* W_g   = (const float*)d_in[3];
    const float* b_g   = (const float*)d_in[4];
    const float* W_a   = (const float*)d_in[5];
    const float* b_a   = (const float*)d_in[6];
    const float* W_b   = (const float*)d_in[7];
    const float* b_b   = (const float*)d_in[8];
    const float* W_c   = (const float*)d_in[9];
    const float* b_c   = (const float*)d_in[10];
    const float* W_cls = (const float*)d_in[11];
    const float* b_cls = (const float*)d_in[12];
    float* out = (float*)d_out;

    static bool attr_set = false;
    if (!attr_set) {
        cudaFuncSetAttribute(gram_topk, cudaFuncAttributeMaxDynamicSharedMemorySize,
                             GRAM_DSMEM);
        attr_set = true;
    }

    void *px, *pP, *pQ, *pg, *pAp, *pBp;
    cudaGetSymbolAddress(&px, d_x);
    cudaGetSymbolAddress(&pP, d_P);
    cudaGetSymbolAddress(&pQ, d_Q);
    cudaGetSymbolAddress(&pg, d_g);
    cudaGetSymbolAddress(&pAp, d_Ap);
    cudaGetSymbolAddress(&pBp, d_Bp);
    float* x  = (float*)px;
    float* P  = (float*)pP;
    float* Q  = (float*)pQ;
    float* g  = (float*)pg;
    float* Ap = (float*)pAp;
    float* Bp = (float*)pBp;

    // 1. x = relu(h @ W_fc + b_fc)  — fp32 FFMA exact (kNN-critical)
    gemm_f32_relu<<<dim3(HD / FBN, MROWS / FBM), 256>>>(h, W_fc, b_fc, x, MROWS, DIM, HD);
    // 2. squared norms
    sqnorm_kernel<<<MROWS, 128>>>();
    // 3. fused Gram(bf16-3x) + per-tile top-KC (no d2 materialization)
    gram_topk<<<dim3(NTILE, NTILE, NB), 256, GRAM_DSMEM>>>(x);
    // 4a. merge partial candidates -> approx top-KC
    merge_cand_kernel<<<MROWS / 4, 128>>>();
    // 4b. exact fp32 re-rank -> top-KN
    rerank_kernel<<<MROWS, KC * 32>>>();
    // 5/6. P = x@Wg_top, Q = x@Wg_bot — bf16-3x
    gemm_bf<<<dim3(HD / XBN, MROWS / XBM), 256>>>(x, W_g, P, MROWS, HD, HD);
    gemm_bf<<<dim3(HD / XBN, MROWS / XBM), 256>>>(x, W_g + (size_t)HD * HD, Q, MROWS, HD, HD);
    // 7. edgeconv gather + max (b_g added here)
    edgeconv_kernel<<<MROWS, 128>>>(b_g);
    // 8/9. attention pre-projections — bf16-3x (biases added in gate)
    gemm_bf<<<dim3(DA / XBN, MROWS / XBM), 256>>>(g, W_a, Ap, MROWS, HD, DA);
    gemm_bf<<<dim3(DA / XBN, MROWS / XBM), 256>>>(g, W_b, Bp, MROWS, HD, DA);
    // 10. gated attention score -> A_raw
    gate_kernel<<<MROWS, 128>>>(b_a, b_b, W_c, b_c, out);
    // 11. softmax stats + zero M
    attn_stats_kernel<<<NB, 512>>>();
    // 12. chunked weighted pooling
    pool_acc_kernel<<<dim3(NB, 16), 256>>>();
    // 13. classifier head + Y_prob
    head_kernel<<<NB, 128>>>(W_cls, b_cls, out);
}

// round 13
// speedup vs baseline: 1.6570x; 1.6570x over previous
#include <cuda_runtime.h>
#include <cuda_bf16.h>
#include <math.h>
#include <cstdint>

constexpr int NB  = 8;
constexpr int NI  = 2048;
constexpr int DIM = 1024;
constexpr int HD  = 512;
constexpr int DA  = 256;
constexpr int KN  = 5;
constexpr int KC  = 9;      // candidates for exact re-rank
constexpr int NC  = 2;
constexpr int MROWS = NB * NI;   // 16384

// Scratch (static device globals)
__device__ float d_x [MROWS * HD];
__device__ float d_sq[MROWS];
__device__ float d_d2[(size_t)NB * NI * NI];   // 128 MB
__device__ int   d_cand[MROWS * KC];
__device__ int   d_idx[MROWS * KN];
__device__ float d_P [MROWS * HD];
__device__ float d_Q [MROWS * HD];
__device__ float d_g [MROWS * HD];
__device__ float d_Ap[MROWS * DA];
__device__ float d_Bp[MROWS * DA];
__device__ float d_Ar[MROWS];
__device__ float d_M [NB * HD];
// pre-split bf16 operands (u32 = {even k (lo16), odd k (hi16)})
__device__ uint32_t d_xhi[MROWS * HD / 2];
__device__ uint32_t d_xlo[MROWS * HD / 2];
__device__ uint32_t d_ghi[MROWS * HD / 2];
__device__ uint32_t d_glo[MROWS * HD / 2];
__device__ uint32_t d_wgthi[(HD / 2) * HD];
__device__ uint32_t d_wgtlo[(HD / 2) * HD];
__device__ uint32_t d_wgbhi[(HD / 2) * HD];
__device__ uint32_t d_wgblo[(HD / 2) * HD];
__device__ uint32_t d_wahi[(HD / 2) * DA];
__device__ uint32_t d_walo[(HD / 2) * DA];
__device__ uint32_t d_wbhi[(HD / 2) * DA];
__device__ uint32_t d_wblo[(HD / 2) * DA];

// ===========================================================================
// PART 1: fp32 FFMA GEMM (exact) — fc layer only (kNN-critical x).
// ===========================================================================
constexpr int FBM = 128, FBN = 128, FBK = 8;

__global__ __launch_bounds__(256, 2)
void gemm_f32_relu(const float* __restrict__ A, const float* __restrict__ Bm,
                   const float* __restrict__ bias, float* __restrict__ Cm,
                   int M, int Kd, int Nd) {
    __shared__ float As[2][FBK][FBM];
    __shared__ float Bs[2][FBK][FBN];
    const int tid = threadIdx.x;
    const int tx = tid & 15, ty = tid >> 4;
    const int rowBase = blockIdx.y * FBM;
    const int colBase = blockIdx.x * FBN;
    const int arow = tid >> 1, acol = (tid & 1) * 4;
    const int brow = tid >> 5, bcol = (tid & 31) * 4;

    float4 aR = *(const float4*)(A + (size_t)(rowBase + arow) * Kd + acol);
    float4 bR = *(const float4*)(Bm + (size_t)brow * Nd + colBase + bcol);
    As[0][acol + 0][arow] = aR.x; As[0][acol + 1][arow] = aR.y;
    As[0][acol + 2][arow] = aR.z; As[0][acol + 3][arow] = aR.w;
    *(float4*)&Bs[0][brow][bcol] = bR;
    __syncthreads();

    float acc[8][8];
#pragma unroll
    for (int m = 0; m < 8; m++)
#pragma unroll
        for (int n = 0; n < 8; n++) acc[m][n] = 0.f;

    const int KT = Kd / FBK;
    for (int kt = 0; kt < KT; kt++) {
        const int cur = kt & 1;
        if (kt + 1 < KT) {
            const int k0 = (kt + 1) * FBK;
            aR = *(const float4*)(A + (size_t)(rowBase + arow) * Kd + k0 + acol);
            bR = *(const float4*)(Bm + (size_t)(k0 + brow) * Nd + colBase + bcol);
        }
#pragma unroll
        for (int kk = 0; kk < FBK; kk++) {
            float4 a0 = *(const float4*)&As[cur][kk][ty * 4];
            float4 a1 = *(const float4*)&As[cur][kk][64 + ty * 4];
            float4 b0 = *(const float4*)&Bs[cur][kk][tx * 4];
            float4 b1 = *(const float4*)&Bs[cur][kk][64 + tx * 4];
            float av[8] = {a0.x, a0.y, a0.z, a0.w, a1.x, a1.y, a1.z, a1.w};
            float bv[8] = {b0.x, b0.y, b0.z, b0.w, b1.x, b1.y, b1.z, b1.w};
#pragma unroll
            for (int m = 0; m < 8; m++)
#pragma unroll
                for (int n = 0; n < 8; n++)
                    acc[m][n] = fmaf(av[m], bv[n], acc[m][n]);
        }
        if (kt + 1 < KT) {
            const int nxt = cur ^ 1;
            As[nxt][acol + 0][arow] = aR.x; As[nxt][acol + 1][arow] = aR.y;
            As[nxt][acol + 2][arow] = aR.z; As[nxt][acol + 3][arow] = aR.w;
            *(float4*)&Bs[nxt][brow][bcol] = bR;
            __syncthreads();
        }
    }

#pragma unroll
    for (int m = 0; m < 8; m++) {
        const int r = rowBase + ((m < 4) ? (ty * 4 + m) : (64 + ty * 4 + (m - 4)));
        const int c0 = colBase + tx * 4;
        const int c1 = colBase + 64 + tx * 4;
        float4 t0 = *(const float4*)&bias[c0];
        float4 t1 = *(const float4*)&bias[c1];
        float4 v0, v1;
        v0.x = fmaxf(acc[m][0] + t0.x, 0.f); v0.y = fmaxf(acc[m][1] + t0.y, 0.f);
        v0.z = fmaxf(acc[m][2] + t0.z, 0.f); v0.w = fmaxf(acc[m][3] + t0.w, 0.f);
        v1.x = fmaxf(acc[m][4] + t1.x, 0.f); v1.y = fmaxf(acc[m][5] + t1.y, 0.f);
        v1.z = fmaxf(acc[m][6] + t1.z, 0.f); v1.w = fmaxf(acc[m][7] + t1.w, 0.f);
        *(float4*)&Cm[(size_t)r * Nd + c0] = v0;
        *(float4*)&Cm[(size_t)r * Nd + c1] = v1;
    }
}

// ===========================================================================
// bf16 split helpers + pre-split kernels
// ===========================================================================
__device__ __forceinline__ uint32_t pack_hi(float a, float b, float& la, float& lb) {
    __nv_bfloat16 ha = __float2bfloat16_rn(a);
    __nv_bfloat16 hb = __float2bfloat16_rn(b);
    la = a - __bfloat162float(ha);
    lb = b - __bfloat162float(hb);
    return ((uint32_t)__bfloat16_as_ushort(hb) << 16) | __bfloat16_as_ushort(ha);
}
__device__ __forceinline__ uint32_t pack_lo(float la, float lb) {
    __nv_bfloat16 a = __float2bfloat16_rn(la);
    __nv_bfloat16 b = __float2bfloat16_rn(lb);
    return ((uint32_t)__bfloat16_as_ushort(b) << 16) | __bfloat16_as_ushort(a);
}

// row-major tensor [M x Kd] -> u32 k-pair arrays [M x Kd/2]
__global__ void split_kernel(const float* __restrict__ src,
                             uint32_t* __restrict__ hi, uint32_t* __restrict__ lo) {
    const int idx = blockIdx.x * blockDim.x + threadIdx.x;   // 4 floats each
    float4 v = ((const float4*)src)[idx];
    float l0, l1, l2, l3;
    uint32_t h01 = pack_hi(v.x, v.y, l0, l1);
    uint32_t h23 = pack_hi(v.z, v.w, l2, l3);
    ((uint2*)hi)[idx] = make_uint2(h01, h23);
    ((uint2*)lo)[idx] = make_uint2(pack_lo(l0, l1), pack_lo(l2, l3));
}

// weight [Kd x Nd] row-major -> k-pair-interleaved u32 [Kd/2 x Nd]
__global__ void splitw_kernel(const float* __restrict__ W,
                              uint32_t* __restrict__ hi, uint32_t* __restrict__ lo,
                              int Nd) {
    const int idx = blockIdx.x * blockDim.x + threadIdx.x;   // one (kp, c4)
    const int nc4 = Nd >> 2;
    const int kp = idx / nc4, c4 = (idx - kp * nc4) * 4;
    float4 r0 = *(const float4*)(W + (size_t)(2 * kp) * Nd + c4);
    float4 r1 = *(const float4*)(W + (size_t)(2 * kp + 1) * Nd + c4);
    float a0, a1, a2, a3, a4, a5, a6, a7;
    uint32_t h0 = pack_hi(r0.x, r1.x, a0, a1);
    uint32_t h1 = pack_hi(r0.y, r1.y, a2, a3);
    uint32_t h2 = pack_hi(r0.z, r1.z, a4, a5);
    uint32_t h3 = pack_hi(r0.w, r1.w, a6, a7);
    *(uint4*)&hi[(size_t)kp * Nd + c4] = make_uint4(h0, h1, h2, h3);
    *(uint4*)&lo[(size_t)kp * Nd + c4] =
        make_uint4(pack_lo(a0, a1), pack_lo(a2, a3), pack_lo(a4, a5), pack_lo(a6, a7));
}

// ===========================================================================
// PART 2: bf16-3x GEMM on pre-split operands.
// D += Ahi*Bhi + Ahi*Blo + Alo*Bhi.
// EPI: 0 = plain A@B, 2 = per-bag Gram -> d2 + symmetric mirror.
// TRB: B in row-major k-pair form [Nd x Kd/2] (same as A); else [Kd/2 x Nd].
// ===========================================================================
constexpr int XBM = 128, XBN = 128, XBK = 16;
constexpr int LDW = 136;
constexpr int ARR = 8 * LDW;

__device__ __forceinline__ void mma_bf16(float* c, uint32_t a0, uint32_t a1,
                                         uint32_t a2, uint32_t a3,
                                         uint32_t b0, uint32_t b1) {
    asm volatile(
        "mma.sync.aligned.m16n8k16.row.col.f32.bf16.bf16.f32 "
        "{%0,%1,%2,%3}, {%4,%5,%6,%7}, {%8,%9}, {%0,%1,%2,%3};\n"
        : "+f"(c[0]), "+f"(c[1]), "+f"(c[2]), "+f"(c[3])
        : "r"(a0), "r"(a1), "r"(a2), "r"(a3), "r"(b0), "r"(b1));
}

template <int EPI, int TRB>
__global__ __launch_bounds__(256, 2)
void gemm_bf2(const uint32_t* __restrict__ AhiAll, const uint32_t* __restrict__ AloAll,
              const uint32_t* __restrict__ BhiAll, const uint32_t* __restrict__ BloAll,
              float* __restrict__ Call, int M, int Kd, int Nd) {
    const int bx = blockIdx.x, by = blockIdx.y;
    const uint32_t* Ahi = AhiAll;
    const uint32_t* Alo = AloAll;
    const uint32_t* Bhi = BhiAll;
    const uint32_t* Blo = BloAll;
    float* C = Call;
    const float* sqb = nullptr;
    if (EPI == 2) {
        if (by > bx) return;
        const int bag = blockIdx.z;
        Ahi = AhiAll + (size_t)bag * NI * (HD / 2);
        Alo = AloAll + (size_t)bag * NI * (HD / 2);
        Bhi = Ahi; Blo = Alo;
        C = Call + (size_t)bag * NI * NI;
        sqb = d_sq + bag * NI;
    }
    const int rowBase = by * XBM, colBase = bx * XBN;
    const int KH = Kd >> 1;

    __shared__ uint32_t S[2][4][ARR];

    const int tid = threadIdx.x;
    const int lane = tid & 31;
    const int grp = lane >> 2;
    const int tig = lane & 3;
    const int warpId = tid >> 5;
    const int wm = (warpId & 1) * 64;
    const int wn = (warpId >> 1) * 32;

    const int sa_row = tid >> 3;     // 0..31
    const int sa_k2  = tid & 7;      // 0..7 (k-pair)
    const int sb_k2  = tid >> 5;     // 0..7 (non-TRB)
    const int sb_n   = (tid & 31) * 4;

    uint32_t ah[4], al[4], bh[4], bl[4];
    uint4 th, tl;

    auto gload = [&](int k0) {
        const int kp = (k0 >> 1) + sa_k2;
#pragma unroll
        for (int p = 0; p < 4; p++) {
            const size_t off = (size_t)(rowBase + p * 32 + sa_row) * KH + kp;
            ah[p] = Ahi[off];
            al[p] = Alo[off];
        }
        if (TRB) {
#pragma unroll
            for (int p = 0; p < 4; p++) {
                const size_t off = (size_t)(colBase + p * 32 + sa_row) * KH + kp;
                bh[p] = Bhi[off];
                bl[p] = Blo[off];
            }
        } else {
            const size_t off = (size_t)((k0 >> 1) + sb_k2) * Nd + colBase + sb_n;
            th = *(const uint4*)&Bhi[off];
            tl = *(const uint4*)&Blo[off];
        }
    };
    auto sstore = [&](int buf) {
#pragma unroll
        for (int p = 0; p < 4; p++) {
            const int row = p * 32 + sa_row;
            S[buf][0][sa_k2 * LDW + row] = ah[p];
            S[buf][1][sa_k2 * LDW + row] = al[p];
        }
        if (TRB) {
#pragma unroll
            for (int p = 0; p < 4; p++) {
                const int n = p * 32 + sa_row;
                S[buf][2][sa_k2 * LDW + n] = bh[p];
                S[buf][3][sa_k2 * LDW + n] = bl[p];
            }
        } else {
            *(uint4*)&S[buf][2][sb_k2 * LDW + sb_n] = th;
            *(uint4*)&S[buf][3][sb_k2 * LDW + sb_n] = tl;
        }
    };

    gload(0);
    sstore(0);
    __syncthreads();

    float acc[4][4][4];
#pragma unroll
    for (int mi = 0; mi < 4; mi++)
#pragma unroll
        for (int ni = 0; ni < 4; ni++)
#pragma unroll
            for (int q = 0; q < 4; q++) acc[mi][ni][q] = 0.f;

    const int KT = Kd / XBK;
    for (int kt = 0; kt < KT; kt++) {
        const int cur = kt & 1;
        if (kt + 1 < KT) gload((kt + 1) * XBK);

        uint32_t bhi[4][2], blo[4][2];
#pragma unroll
        for (int ni = 0; ni < 4; ni++) {
            const int n = wn + ni * 8 + grp;
            bhi[ni][0] = S[cur][2][tig * LDW + n];
            bhi[ni][1] = S[cur][2][(tig + 4) * LDW + n];
            blo[ni][0] = S[cur][3][tig * LDW + n];
            blo[ni][1] = S[cur][3][(tig + 4) * LDW + n];
        }
#pragma unroll
        for (int mi = 0; mi < 4; mi++) {
            const int r = wm + mi * 16 + grp;
            uint32_t ah0 = S[cur][0][tig * LDW + r];
            uint32_t ah1 = S[cur][0][tig * LDW + r + 8];
            uint32_t ah2 = S[cur][0][(tig + 4) * LDW + r];
            uint32_t ah3 = S[cur][0][(tig + 4) * LDW + r + 8];
            uint32_t al0 = S[cur][1][tig * LDW + r];
            uint32_t al1 = S[cur][1][tig * LDW + r + 8];
            uint32_t al2 = S[cur][1][(tig + 4) * LDW + r];
            uint32_t al3 = S[cur][1][(tig + 4) * LDW + r + 8];
#pragma unroll
            for (int ni = 0; ni < 4; ni++) {
                mma_bf16(acc[mi][ni], ah0, ah1, ah2, ah3, bhi[ni][0], bhi[ni][1]);
                mma_bf16(acc[mi][ni], ah0, ah1, ah2, ah3, blo[ni][0], blo[ni][1]);
                mma_bf16(acc[mi][ni], al0, al1, al2, al3, bhi[ni][0], bhi[ni][1]);
            }
        }
        if (kt + 1 < KT) {
            sstore(cur ^ 1);
            __syncthreads();
        }
    }

    // ---- epilogue ----
#pragma unroll
    for (int mi = 0; mi < 4; mi++) {
        const int row = rowBase + wm + mi * 16 + grp;
#pragma unroll
        for (int ni = 0; ni < 4; ni++) {
            const int col = colBase + wn + ni * 8 + tig * 2;
            float c0 = acc[mi][ni][0], c1 = acc[mi][ni][1];
            float c2 = acc[mi][ni][2], c3 = acc[mi][ni][3];
            if (EPI == 2) {
                const float sr0 = sqb[row], sr8 = sqb[row + 8];
                const float sc0 = sqb[col], sc1 = sqb[col + 1];
                float2 v0, v1;
                v0.x = sr0 + sc0 - 2.f * c0;  v0.y = sr0 + sc1 - 2.f * c1;
                v1.x = sr8 + sc0 - 2.f * c2;  v1.y = sr8 + sc1 - 2.f * c3;
                *(float2*)&C[(size_t)row * Nd + col] = v0;
                *(float2*)&C[(size_t)(row + 8) * Nd + col] = v1;
                if (bx != by) {
                    C[(size_t)col * Nd + row]           = v0.x;
                    C[(size_t)col * Nd + row + 8]       = v1.x;
                    C[(size_t)(col + 1) * Nd + row]     = v0.y;
                    C[(size_t)(col + 1) * Nd + row + 8] = v1.y;
                }
            } else {
                float2 v0; v0.x = c0; v0.y = c1;
                float2 v1; v1.x = c2; v1.y = c3;
                *(float2*)&C[(size_t)row * Nd + col] = v0;
                *(float2*)&C[(size_t)(row + 8) * Nd + col] = v1;
            }
        }
    }
}

// ---------------------------------------------------------------------------
// Row squared norms
// ---------------------------------------------------------------------------
__global__ void sqnorm_kernel() {
    const int row = blockIdx.x, tid = threadIdx.x;
    __shared__ float sh[4];
    const float* xr = d_x + (size_t)row * HD;
    float4 v = *(const float4*)(xr + tid * 4);
    float s = v.x * v.x + v.y * v.y + v.z * v.z + v.w * v.w;
    const int lane = tid & 31, w = tid >> 5;
#pragma unroll
    for (int o = 16; o > 0; o >>= 1) s += __shfl_down_sync(0xffffffffu, s, o);
    if (lane == 0) sh[w] = s;
    __syncthreads();
    if (tid == 0) d_sq[row] = sh[0] + sh[1] + sh[2] + sh[3];
}

// ---------------------------------------------------------------------------
// Approx top-KC candidates per row. 8 warps/block, 1 warp/row, 8 els/lane/iter.
// ---------------------------------------------------------------------------
__global__ __launch_bounds__(256)
void topk_kernel() {
    const int w = threadIdx.x >> 5;
    const int lane = threadIdx.x & 31;
    const int row = blockIdx.x * 8 + w;
    const int b = row >> 11;
    const int i = row & (NI - 1);
    const float* drow = d_d2 + (size_t)b * NI * NI + (size_t)i * NI;

    float bd[KC]; int bix[KC];
#pragma unroll
    for (int k = 0; k < KC; k++) { bd[k] = 3.4e38f; bix[k] = 0x7fffffff; }

    for (int j0 = lane * 8; j0 < NI; j0 += 256) {
        float4 da = *(const float4*)(drow + j0);
        float4 db = *(const float4*)(drow + j0 + 4);
        float vs[8] = {da.x, da.y, da.z, da.w, db.x, db.y, db.z, db.w};
#pragma unroll
        for (int t = 0; t < 8; t++) {
            float v = vs[t];
            if (v < bd[KC - 1]) {
                bd[KC - 1] = v; bix[KC - 1] = j0 + t;
#pragma unroll
                for (int q = KC - 1; q > 0; q--) {
                    if (bd[q] < bd[q - 1]) {
                        float tf = bd[q]; bd[q] = bd[q - 1]; bd[q - 1] = tf;
                        int ti = bix[q]; bix[q] = bix[q - 1]; bix[q - 1] = ti;
                    }
                }
            }
        }
    }

    int* oc = d_cand + (size_t)row * KC;
    int cp = 0;
    float cv = bd[0]; int ci = bix[0];
#pragma unroll
    for (int k = 0; k < KC; k++) {
        float rv = cv; int ri = ci;
#pragma unroll
        for (int off = 16; off > 0; off >>= 1) {
            float ov = __shfl_xor_sync(0xffffffffu, rv, off);
            int   oj = __shfl_xor_sync(0xffffffffu, ri, off);
            if (ov < rv || (ov == rv && oj < ri)) { rv = ov; ri = oj; }
        }
        if (lane == 0) oc[k] = ri;
        if (cv == rv && ci == ri) {
            cp++;
            float nv = 3.4e38f; int ni2 = 0x7fffffff;
#pragma unroll
            for (int q = 1; q < KC; q++) if (cp == q) { nv = bd[q]; ni2 = bix[q]; }
            cv = nv; ci = ni2;
        }
    }
}

// ---------------------------------------------------------------------------
// Exact fp32 re-rank of KC candidates -> true top-KN.
// ---------------------------------------------------------------------------
__global__ void rerank_kernel() {
    const int row = blockIdx.x;
    const int b = row >> 11;
    const int wid = threadIdx.x >> 5, lane = threadIdx.x & 31;
    __shared__ float sval[KC];
    __shared__ int   sidx[KC];

    if (wid < KC) {
        const int j = d_cand[(size_t)row * KC + wid];
        const float* xi = d_x + (size_t)row * HD;
        const float* xj = d_x + (size_t)(b * NI + j) * HD;
        float acc = 0.f;
#pragma unroll
        for (int t = 0; t < 4; t++) {
            float4 a = *(const float4*)(xi + (lane + t * 32) * 4);
            float4 c = *(const float4*)(xj + (lane + t * 32) * 4);
            acc += a.x * c.x + a.y * c.y + a.z * c.z + a.w * c.w;
        }
#pragma unroll
        for (int o = 16; o > 0; o >>= 1) acc += __shfl_down_sync(0xffffffffu, acc, o);
        if (lane == 0) {
            sval[wid] = d_sq[b * NI + j] - 2.f * acc;
            sidx[wid] = j;
        }
    }
    __syncthreads();
    if (threadIdx.x == 0) {
        int* oi = d_idx + (size_t)row * KN;
        bool used[KC];
#pragma unroll
        for (int k = 0; k < KC; k++) used[k] = false;
#pragma unroll
        for (int k = 0; k < KN; k++) {
            float best = 3.5e38f; int bi = 0x7fffffff; int bp = 0;
#pragma unroll
            for (int t = 0; t < KC; t++) {
                if (!used[t]) {
                    float v = sval[t]; int ii = sidx[t];
                    if (v < best || (v == best && ii < bi)) { best = v; bi = ii; bp = t; }
                }
            }
            used[bp] = true;
            oi[k] = bi;
        }
    }
}

// ---------------------------------------------------------------------------
// EdgeConv: g[row,h] = max_k relu(P - Q + b_g + Q[nbr_k])
// ---------------------------------------------------------------------------
__global__ void edgeconv_kernel(const float* __restrict__ bgv) {
    const int row = blockIdx.x;
    const int b = row >> 11;
    const int tid = threadIdx.x;
    __shared__ int sj[KN];
    if (tid < KN) sj[tid] = d_idx[(size_t)row * KN + tid];
    __syncthreads();
    const int hh = tid * 4;
    float4 p  = *(const float4*)(d_P + (size_t)row * HD + hh);
    float4 q  = *(const float4*)(d_Q + (size_t)row * HD + hh);
    float4 bg = *(const float4*)(bgv + hh);
    float bx_ = p.x - q.x + bg.x;
    float by_ = p.y - q.y + bg.y;
    float bz_ = p.z - q.z + bg.z;
    float bw_ = p.w - q.w + bg.w;
    float mx = 0.f, my = 0.f, mz = 0.f, mw = 0.f;
    const float* Qb = d_Q + (size_t)b * NI * HD;
#pragma unroll
    for (int k = 0; k < KN; k++) {
        float4 qk = *(const float4*)(Qb + (size_t)sj[k] * HD + hh);
        mx = fmaxf(mx, bx_ + qk.x);
        my = fmaxf(my, by_ + qk.y);
        mz = fmaxf(mz, bz_ + qk.z);
        mw = fmaxf(mw, bw_ + qk.w);
    }
    float4 o; o.x = mx; o.y = my; o.z = mz; o.w = mw;
    *(float4*)(d_g + (size_t)row * HD + hh) = o;
}

__device__ __forceinline__ float blockReduceSum(float v, float* sh) {
    int lane = threadIdx.x & 31, w = threadIdx.x >> 5;
#pragma unroll
    for (int o = 16; o > 0; o >>= 1) v += __shfl_down_sync(0xffffffffu, v, o);
    if (lane == 0) sh[w] = v;
    __syncthreads();
    int nw = blockDim.x >> 5;
    v = (threadIdx.x < nw) ? sh[threadIdx.x] : 0.f;
    if (w == 0)
#pragma unroll
        for (int o = 16; o > 0; o >>= 1) v += __shfl_down_sync(0xffffffffu, v, o);
    return v;
}

// ---------------------------------------------------------------------------
// Gated attention score -> A_raw
// ---------------------------------------------------------------------------
__global__ void gate_kernel(const float* __restrict__ ba, const float* __restrict__ bb,
                            const float* __restrict__ Wc, const float* __restrict__ bc,
                            float* __restrict__ out) {
    const int row = blockIdx.x, tid = threadIdx.x;
    __shared__ float sh[32];
    const float* ap = d_Ap + (size_t)row * DA;
    const float* bp = d_Bp + (size_t)row * DA;
    float s = 0.f;
    for (int dd = tid; dd < DA; dd += 128) {
        float av = tanhf(ap[dd] + ba[dd]);
        float bv = bp[dd] + bb[dd];
        bv = 1.f / (1.f + expf(-bv));
        s += av * bv * Wc[dd];
    }
    s = blockReduceSum(s, sh);
    if (tid == 0) {
        float v = s + bc[0];
        d_Ar[row] = v;
        out[2 * NB * NC + row] = v;
    }
}

// ---------------------------------------------------------------------------
// Per-bag softmax stats; zero d_M.
// ---------------------------------------------------------------------------
__global__ void attn_stats_kernel() {
    const int b = blockIdx.x, tid = threadIdx.x;
    __shared__ float red[512];
    float* Ar = d_Ar + (size_t)b * NI;

    float mx = -3.4e38f;
    for (int n = tid; n < NI; n += 512) mx = fmaxf(mx, Ar[n]);
    red[tid] = mx; __syncthreads();
    for (int s = 256; s > 0; s >>= 1) { if (tid < s) red[tid] = fmaxf(red[tid], red[tid + s]); __syncthreads(); }
    mx = red[0];
    __syncthreads();

    float sum = 0.f;
    for (int n = tid; n < NI; n += 512) sum += expf(Ar[n] - mx);
    red[tid] = sum; __syncthreads();
    for (int s = 256; s > 0; s >>= 1) { if (tid < s) red[tid] += red[tid + s]; __syncthreads(); }
    const float inv = 1.f / red[0];
    __syncthreads();

    for (int n = tid; n < NI; n += 512) Ar[n] = expf(Ar[n] - mx) * inv;
    d_M[b * HD + tid] = 0.f;
}

// ---------------------------------------------------------------------------
// Chunked weighted pooling with atomics
// ---------------------------------------------------------------------------
__global__ void pool_acc_kernel() {
    const int b = blockIdx.x, ch = blockIdx.y, tid = threadIdx.x;
    const float* w  = d_Ar + (size_t)b * NI + ch * 128;
    const float* gb = d_g + ((size_t)b * NI + (size_t)ch * 128) * HD;
    __shared__ float ws[128];
    if (tid < 128) ws[tid] = w[tid];
    __syncthreads();
    const int c0 = tid, c1 = tid + 256;
    float a0 = 0.f, a1 = 0.f;
    for (int n = 0; n < 128; n++) {
        const float wn = ws[n];
        a0 = fmaf(wn, gb[(size_t)n * HD + c0], a0);
        a1 = fmaf(wn, gb[(size_t)n * HD + c1], a1);
    }
    atomicAdd(&d_M[b * HD + c0], a0);
    atomicAdd(&d_M[b * HD + c1], a1);
}

// ---------------------------------------------------------------------------
// Classifier head + Y_prob
// ---------------------------------------------------------------------------
__global__ void head_kernel(const float* __restrict__ Wcls, const float* __restrict__ bcls,
                            float* __restrict__ out) {
    const int b = blockIdx.x, tid = threadIdx.x;
    __shared__ float sh[32];
    float s0 = 0.f, s1 = 0.f;
    for (int hh = tid; hh < HD; hh += 128) {
        float m = d_M[b * HD + hh];
        s0 = fmaf(m, Wcls[hh * NC + 0], s0);
        s1 = fmaf(m, Wcls[hh * NC + 1], s1);
    }
    s0 = blockReduceSum(s0, sh);
    __syncthreads();
    s1 = blockReduceSum(s1, sh);
    if (tid == 0) {
        float l0 = s0 + bcls[0], l1 = s1 + bcls[1];
        out[b * NC + 0] = l0;
        out[b * NC + 1] = l1;
        float mx = fmaxf(l0, l1);
        float e0 = expf(l0 - mx), e1 = expf(l1 - mx);
        float inv = 1.f / (e0 + e1);
        out[NB * NC + b * NC + 0] = e0 * inv;
        out[NB * NC + b * NC + 1] = e1 * inv;
    }
}

// ---------------------------------------------------------------------------
extern "C" void kernel_launch(void* const* d_in, const int* in_sizes, int n_in,
                              void* d_out, int out_size) {
    const float* h     = (const float*)d_in[0];
    const float* W_fc  = (const float*)d_in[1];
    const float* b_fc  = (const float*)d_in[2];
    const float* W_g   = (const float*)d_in[3];
    const float* b_g   = (const float*)d_in[4];
    const float* W_a   = (const float*)d_in[5];
    const float* b_a   = (const float*)d_in[6];
    const float* W_b   = (const float*)d_in[7];
    const float* b_b   = (const float*)d_in[8];
    const float* W_c   = (const float*)d_in[9];
    const float* b_c   = (const float*)d_in[10];
    const float* W_cls = (const float*)d_in[11];
    const float* b_cls = (const float*)d_in[12];
    float* out = (float*)d_out;

    void *px, *pP, *pQ, *pg, *pAp, *pBp, *pd2;
    void *pxh, *pxl, *pgh, *pgl;
    void *pwgth, *pwgtl, *pwgbh, *pwgbl, *pwah, *pwal, *pwbh, *pwbl;
    cudaGetSymbolAddress(&px, d_x);
    cudaGetSymbolAddress(&pP, d_P);
    cudaGetSymbolAddress(&pQ, d_Q);
    cudaGetSymbolAddress(&pg, d_g);
    cudaGetSymbolAddress(&pAp, d_Ap);
    cudaGetSymbolAddress(&pBp, d_Bp);
    cudaGetSymbolAddress(&pd2, d_d2);
    cudaGetSymbolAddress(&pxh, d_xhi);
    cudaGetSymbolAddress(&pxl, d_xlo);
    cudaGetSymbolAddress(&pgh, d_ghi);
    cudaGetSymbolAddress(&pgl, d_glo);
    cudaGetSymbolAddress(&pwgth, d_wgthi);
    cudaGetSymbolAddress(&pwgtl, d_wgtlo);
    cudaGetSymbolAddress(&pwgbh, d_wgbhi);
    cudaGetSymbolAddress(&pwgbl, d_wgblo);
    cudaGetSymbolAddress(&pwah, d_wahi);
    cudaGetSymbolAddress(&pwal, d_walo);
    cudaGetSymbolAddress(&pwbh, d_wbhi);
    cudaGetSymbolAddress(&pwbl, d_wblo);
    float* x  = (float*)px;
    float* P  = (float*)pP;
    float* Q  = (float*)pQ;
    float* g  = (float*)pg;
    float* Ap = (float*)pAp;
    float* Bp = (float*)pBp;
    float* d2 = (float*)pd2;
    uint32_t* xhi = (uint32_t*)pxh; uint32_t* xlo = (uint32_t*)pxl;
    uint32_t* ghi = (uint32_t*)pgh; uint32_t* glo = (uint32_t*)pgl;
    uint32_t* wgthi = (uint32_t*)pwgth; uint32_t* wgtlo = (uint32_t*)pwgtl;
    uint32_t* wgbhi = (uint32_t*)pwgbh; uint32_t* wgblo = (uint32_t*)pwgbl;
    uint32_t* wahi = (uint32_t*)pwah; uint32_t* walo = (uint32_t*)pwal;
    uint32_t* wbhi = (uint32_t*)pwbh; uint32_t* wblo = (uint32_t*)pwbl;

    const int NTILE2 = NI / XBN;   // 16

    // 1. x = relu(h @ W_fc + b_fc)  — fp32 FFMA exact (kNN-critical)
    gemm_f32_relu<<<dim3(HD / FBN, MROWS / FBM), 256>>>(h, W_fc, b_fc, x, MROWS, DIM, HD);
    // 2. squared norms + pre-splits
    sqnorm_kernel<<<MROWS, 128>>>();
    split_kernel<<<(MROWS * HD / 4) / 256, 256>>>(x, xhi, xlo);
    splitw_kernel<<<((HD / 2) * (HD / 4)) / 256, 256>>>(W_g, wgthi, wgtlo, HD);
    splitw_kernel<<<((HD / 2) * (HD / 4)) / 256, 256>>>(W_g + (size_t)HD * HD, wgbhi, wgblo, HD);
    splitw_kernel<<<((HD / 2) * (DA / 4)) / 256, 256>>>(W_a, wahi, walo, DA);
    splitw_kernel<<<((HD / 2) * (DA / 4)) / 256, 256>>>(W_b, wbhi, wblo, DA);
    // 3. per-bag Gram -> approx d2 — bf16-3x on pre-split x (upper + mirror)
    gemm_bf2<2, 1><<<dim3(NTILE2, NTILE2, NB), 256>>>(xhi, xlo, xhi, xlo, d2, NI, HD, NI);
    // 4a. approx top-KC candidates
    topk_kernel<<<MROWS / 8, 256>>>();
    // 4b. exact fp32 re-rank -> top-KN
    rerank_kernel<<<MROWS, KC * 32>>>();
    // 5/6. P = x@Wg_top, Q = x@Wg_bot — bf16-3x pre-split
    gemm_bf2<0, 0><<<dim3(HD / XBN, MROWS / XBM), 256>>>(xhi, xlo, wgthi, wgtlo, P, MROWS, HD, HD);
    gemm_bf2<0, 0><<<dim3(HD / XBN, MROWS / XBM), 256>>>(xhi, xlo, wgbhi, wgblo, Q, MROWS, HD, HD);
    // 7. edgeconv gather + max (b_g added here)
    edgeconv_kernel<<<MROWS, 128>>>(b_g);
    // 8. split g for attention projections
    split_kernel<<<(MROWS * HD / 4) / 256, 256>>>(g, ghi, glo);
    // 9. attention pre-projections — bf16-3x pre-split (biases in gate)
    gemm_bf2<0, 0><<<dim3(DA / XBN, MROWS / XBM), 256>>>(ghi, glo, wahi, walo, Ap, MROWS, HD, DA);
    gemm_bf2<0, 0><<<dim3(DA / XBN, MROWS / XBM), 256>>>(ghi, glo, wbhi, wblo, Bp, MROWS, HD, DA);
    // 10. gated attention score -> A_raw
    gate_kernel<<<MROWS, 128>>>(b_a, b_b, W_c, b_c, out);
    // 11. softmax stats + zero M
    attn_stats_kernel<<<NB, 512>>>();
    // 12. chunked weighted pooling
    pool_acc_kernel<<<dim3(NB, 16), 256>>>();
    // 13. classifier head + Y_prob
    head_kernel<<<NB, 128>>>(W_cls, b_cls, out);
}

// round 14
// speedup vs baseline: 1.8880x; 1.1394x over previous
#include <cuda_runtime.h>
#include <cuda_bf16.h>
#include <math.h>
#include <cstdint>

constexpr int NB  = 8;
constexpr int NI  = 2048;
constexpr int DIM = 1024;
constexpr int HD  = 512;
constexpr int DA  = 256;
constexpr int KN  = 5;
constexpr int KC  = 9;      // candidates for exact re-rank
constexpr int NC  = 2;
constexpr int MROWS = NB * NI;   // 16384

// Scratch (static device globals)
__device__ float d_x [MROWS * HD];
__device__ float d_sq[MROWS];
__device__ float d_d2[(size_t)NB * NI * NI];   // 128 MB
__device__ int   d_cand[MROWS * KC];
__device__ int   d_idx[MROWS * KN];
__device__ float d_P [MROWS * HD];
__device__ float d_Q [MROWS * HD];
__device__ float d_g [MROWS * HD];
__device__ float d_Ap[MROWS * DA];
__device__ float d_Bp[MROWS * DA];
__device__ float d_Ar[MROWS];
__device__ float d_M [NB * HD];

// ===========================================================================
// PART 1: fp32 FFMA GEMM (exact) — fc layer only (kNN-critical x).
// ===========================================================================
constexpr int FBM = 128, FBN = 128, FBK = 8;

__global__ __launch_bounds__(256, 2)
void gemm_f32_relu(const float* __restrict__ A, const float* __restrict__ Bm,
                   const float* __restrict__ bias, float* __restrict__ Cm,
                   int M, int Kd, int Nd) {
    __shared__ float As[2][FBK][FBM];
    __shared__ float Bs[2][FBK][FBN];
    const int tid = threadIdx.x;
    const int tx = tid & 15, ty = tid >> 4;
    const int rowBase = blockIdx.y * FBM;
    const int colBase = blockIdx.x * FBN;
    const int arow = tid >> 1, acol = (tid & 1) * 4;
    const int brow = tid >> 5, bcol = (tid & 31) * 4;

    float4 aR = *(const float4*)(A + (size_t)(rowBase + arow) * Kd + acol);
    float4 bR = *(const float4*)(Bm + (size_t)brow * Nd + colBase + bcol);
    As[0][acol + 0][arow] = aR.x; As[0][acol + 1][arow] = aR.y;
    As[0][acol + 2][arow] = aR.z; As[0][acol + 3][arow] = aR.w;
    *(float4*)&Bs[0][brow][bcol] = bR;
    __syncthreads();

    float acc[8][8];
#pragma unroll
    for (int m = 0; m < 8; m++)
#pragma unroll
        for (int n = 0; n < 8; n++) acc[m][n] = 0.f;

    const int KT = Kd / FBK;
    for (int kt = 0; kt < KT; kt++) {
        const int cur = kt & 1;
        if (kt + 1 < KT) {
            const int k0 = (kt + 1) * FBK;
            aR = *(const float4*)(A + (size_t)(rowBase + arow) * Kd + k0 + acol);
            bR = *(const float4*)(Bm + (size_t)(k0 + brow) * Nd + colBase + bcol);
        }
#pragma unroll
        for (int kk = 0; kk < FBK; kk++) {
            float4 a0 = *(const float4*)&As[cur][kk][ty * 4];
            float4 a1 = *(const float4*)&As[cur][kk][64 + ty * 4];
            float4 b0 = *(const float4*)&Bs[cur][kk][tx * 4];
            float4 b1 = *(const float4*)&Bs[cur][kk][64 + tx * 4];
            float av[8] = {a0.x, a0.y, a0.z, a0.w, a1.x, a1.y, a1.z, a1.w};
            float bv[8] = {b0.x, b0.y, b0.z, b0.w, b1.x, b1.y, b1.z, b1.w};
#pragma unroll
            for (int m = 0; m < 8; m++)
#pragma unroll
                for (int n = 0; n < 8; n++)
                    acc[m][n] = fmaf(av[m], bv[n], acc[m][n]);
        }
        if (kt + 1 < KT) {
            const int nxt = cur ^ 1;
            As[nxt][acol + 0][arow] = aR.x; As[nxt][acol + 1][arow] = aR.y;
            As[nxt][acol + 2][arow] = aR.z; As[nxt][acol + 3][arow] = aR.w;
            *(float4*)&Bs[nxt][brow][bcol] = bR;
            __syncthreads();
        }
    }

#pragma unroll
    for (int m = 0; m < 8; m++) {
        const int r = rowBase + ((m < 4) ? (ty * 4 + m) : (64 + ty * 4 + (m - 4)));
        const int c0 = colBase + tx * 4;
        const int c1 = colBase + 64 + tx * 4;
        float4 t0 = *(const float4*)&bias[c0];
        float4 t1 = *(const float4*)&bias[c1];
        float4 v0, v1;
        v0.x = fmaxf(acc[m][0] + t0.x, 0.f); v0.y = fmaxf(acc[m][1] + t0.y, 0.f);
        v0.z = fmaxf(acc[m][2] + t0.z, 0.f); v0.w = fmaxf(acc[m][3] + t0.w, 0.f);
        v1.x = fmaxf(acc[m][4] + t1.x, 0.f); v1.y = fmaxf(acc[m][5] + t1.y, 0.f);
        v1.z = fmaxf(acc[m][6] + t1.z, 0.f); v1.w = fmaxf(acc[m][7] + t1.w, 0.f);
        *(float4*)&Cm[(size_t)r * Nd + c0] = v0;
        *(float4*)&Cm[(size_t)r * Nd + c1] = v1;
    }
}

// ===========================================================================
// PART 2: bf16-3x GEMM (inline split, round-10 proven).
// D += Ahi*Bhi + Ahi*Blo + Alo*Bhi.
// EPI 0: plain A@B, grid.z selects (B0,C0) or (B1,C1) — fused pair launch.
// EPI 2: per-bag Gram -> d2 + symmetric mirror (grid.z = bag).
// TRB: B row-major [Nd x Kd].
// ===========================================================================
constexpr int XBM = 128, XBN = 128, XBK = 16;
constexpr int LDW = 136;
constexpr int ARR = 8 * LDW;

__device__ __forceinline__ uint32_t pack_hi(float a, float b, float& la, float& lb) {
    __nv_bfloat16 ha = __float2bfloat16_rn(a);
    __nv_bfloat16 hb = __float2bfloat16_rn(b);
    la = a - __bfloat162float(ha);
    lb = b - __bfloat162float(hb);
    return ((uint32_t)__bfloat16_as_ushort(hb) << 16) | __bfloat16_as_ushort(ha);
}
__device__ __forceinline__ uint32_t pack_lo(float la, float lb) {
    __nv_bfloat162 t = __floats2bfloat162_rn(la, lb);
    return *(uint32_t*)&t;
}
__device__ __forceinline__ void mma_bf16(float* c, uint32_t a0, uint32_t a1,
                                         uint32_t a2, uint32_t a3,
                                         uint32_t b0, uint32_t b1) {
    asm volatile(
        "mma.sync.aligned.m16n8k16.row.col.f32.bf16.bf16.f32 "
        "{%0,%1,%2,%3}, {%4,%5,%6,%7}, {%8,%9}, {%0,%1,%2,%3};\n"
        : "+f"(c[0]), "+f"(c[1]), "+f"(c[2]), "+f"(c[3])
        : "r"(a0), "r"(a1), "r"(a2), "r"(a3), "r"(b0), "r"(b1));
}

template <int EPI, int TRB>
__global__ __launch_bounds__(256, 2)
void gemm_bf(const float* __restrict__ Aall, const float* __restrict__ B0,
             const float* __restrict__ B1, float* __restrict__ C0,
             float* __restrict__ C1, int M, int Kd, int Nd) {
    const int bx = blockIdx.x, by = blockIdx.y;
    const float* A = Aall;
    const float* B;
    float* C;
    const float* sqb = nullptr;
    if (EPI == 2) {
        if (by > bx) return;
        const int bag = blockIdx.z;
        A = Aall + (size_t)bag * NI * HD;
        B = A;
        C = C0 + (size_t)bag * NI * NI;
        sqb = d_sq + bag * NI;
    } else {
        B = blockIdx.z ? B1 : B0;
        C = blockIdx.z ? C1 : C0;
    }
    const int rowBase = by * XBM, colBase = bx * XBN;

    __shared__ uint32_t S[2][4][ARR];

    const int tid = threadIdx.x;
    const int lane = tid & 31;
    const int grp = lane >> 2;
    const int tig = lane & 3;
    const int warpId = tid >> 5;
    const int wm = (warpId & 1) * 64;
    const int wn = (warpId >> 1) * 32;

    const int sa_row = tid >> 3;
    const int sa_k2  = tid & 7;
    const int sb_k2  = tid >> 5;
    const int sb_n   = (tid & 31) * 4;

    float2 pa[4], pb[4];
    float4 pw0, pw1;

    auto gload = [&](int k0) {
#pragma unroll
        for (int p = 0; p < 4; p++)
            pa[p] = *(const float2*)(A + (size_t)(rowBase + p * 32 + sa_row) * Kd + k0 + sa_k2 * 2);
        if (TRB) {
#pragma unroll
            for (int p = 0; p < 4; p++)
                pb[p] = *(const float2*)(B + (size_t)(colBase + p * 32 + sa_row) * Kd + k0 + sa_k2 * 2);
        } else {
            const int k = k0 + sb_k2 * 2;
            pw0 = *(const float4*)(B + (size_t)k * Nd + colBase + sb_n);
            pw1 = *(const float4*)(B + (size_t)(k + 1) * Nd + colBase + sb_n);
        }
    };
    auto sstore = [&](int buf) {
#pragma unroll
        for (int p = 0; p < 4; p++) {
            const int row = p * 32 + sa_row;
            float la, lb;
            uint32_t h = pack_hi(pa[p].x, pa[p].y, la, lb);
            S[buf][0][sa_k2 * LDW + row] = h;
            S[buf][1][sa_k2 * LDW + row] = pack_lo(la, lb);
        }
        if (TRB) {
#pragma unroll
            for (int p = 0; p < 4; p++) {
                const int n = p * 32 + sa_row;
                float la, lb;
                uint32_t h = pack_hi(pb[p].x, pb[p].y, la, lb);
                S[buf][2][sa_k2 * LDW + n] = h;
                S[buf][3][sa_k2 * LDW + n] = pack_lo(la, lb);
            }
        } else {
            float l0, l1, l2, l3, l4, l5, l6, l7;
            uint32_t h0 = pack_hi(pw0.x, pw1.x, l0, l1);
            uint32_t h1 = pack_hi(pw0.y, pw1.y, l2, l3);
            uint32_t h2 = pack_hi(pw0.z, pw1.z, l4, l5);
            uint32_t h3 = pack_hi(pw0.w, pw1.w, l6, l7);
            *(uint4*)&S[buf][2][sb_k2 * LDW + sb_n] = make_uint4(h0, h1, h2, h3);
            *(uint4*)&S[buf][3][sb_k2 * LDW + sb_n] =
                make_uint4(pack_lo(l0, l1), pack_lo(l2, l3), pack_lo(l4, l5), pack_lo(l6, l7));
        }
    };

    gload(0);
    sstore(0);
    __syncthreads();

    float acc[4][4][4];
#pragma unroll
    for (int mi = 0; mi < 4; mi++)
#pragma unroll
        for (int ni = 0; ni < 4; ni++)
#pragma unroll
            for (int q = 0; q < 4; q++) acc[mi][ni][q] = 0.f;

    const int KT = Kd / XBK;
    for (int kt = 0; kt < KT; kt++) {
        const int cur = kt & 1;
        if (kt + 1 < KT) gload((kt + 1) * XBK);

        uint32_t bhi[4][2], blo[4][2];
#pragma unroll
        for (int ni = 0; ni < 4; ni++) {
            const int n = wn + ni * 8 + grp;
            bhi[ni][0] = S[cur][2][tig * LDW + n];
            bhi[ni][1] = S[cur][2][(tig + 4) * LDW + n];
            blo[ni][0] = S[cur][3][tig * LDW + n];
            blo[ni][1] = S[cur][3][(tig + 4) * LDW + n];
        }
#pragma unroll
        for (int mi = 0; mi < 4; mi++) {
            const int r = wm + mi * 16 + grp;
            uint32_t ah0 = S[cur][0][tig * LDW + r];
            uint32_t ah1 = S[cur][0][tig * LDW + r + 8];
            uint32_t ah2 = S[cur][0][(tig + 4) * LDW + r];
            uint32_t ah3 = S[cur][0][(tig + 4) * LDW + r + 8];
            uint32_t al0 = S[cur][1][tig * LDW + r];
            uint32_t al1 = S[cur][1][tig * LDW + r + 8];
            uint32_t al2 = S[cur][1][(tig + 4) * LDW + r];
            uint32_t al3 = S[cur][1][(tig + 4) * LDW + r + 8];
#pragma unroll
            for (int ni = 0; ni < 4; ni++) {
                mma_bf16(acc[mi][ni], ah0, ah1, ah2, ah3, bhi[ni][0], bhi[ni][1]);
                mma_bf16(acc[mi][ni], ah0, ah1, ah2, ah3, blo[ni][0], blo[ni][1]);
                mma_bf16(acc[mi][ni], al0, al1, al2, al3, bhi[ni][0], bhi[ni][1]);
            }
        }
        if (kt + 1 < KT) {
            sstore(cur ^ 1);
            __syncthreads();
        }
    }

    // ---- epilogue ----
#pragma unroll
    for (int mi = 0; mi < 4; mi++) {
        const int row = rowBase + wm + mi * 16 + grp;
#pragma unroll
        for (int ni = 0; ni < 4; ni++) {
            const int col = colBase + wn + ni * 8 + tig * 2;
            float c0 = acc[mi][ni][0], c1 = acc[mi][ni][1];
            float c2 = acc[mi][ni][2], c3 = acc[mi][ni][3];
            if (EPI == 2) {
                const float sr0 = sqb[row], sr8 = sqb[row + 8];
                const float sc0 = sqb[col], sc1 = sqb[col + 1];
                float2 v0, v1;
                v0.x = sr0 + sc0 - 2.f * c0;  v0.y = sr0 + sc1 - 2.f * c1;
                v1.x = sr8 + sc0 - 2.f * c2;  v1.y = sr8 + sc1 - 2.f * c3;
                *(float2*)&C[(size_t)row * Nd + col] = v0;
                *(float2*)&C[(size_t)(row + 8) * Nd + col] = v1;
                if (bx != by) {
                    C[(size_t)col * Nd + row]           = v0.x;
                    C[(size_t)col * Nd + row + 8]       = v1.x;
                    C[(size_t)(col + 1) * Nd + row]     = v0.y;
                    C[(size_t)(col + 1) * Nd + row + 8] = v1.y;
                }
            } else {
                float2 v0; v0.x = c0; v0.y = c1;
                float2 v1; v1.x = c2; v1.y = c3;
                *(float2*)&C[(size_t)row * Nd + col] = v0;
                *(float2*)&C[(size_t)(row + 8) * Nd + col] = v1;
            }
        }
    }
}

// ---------------------------------------------------------------------------
// Row squared norms
// ---------------------------------------------------------------------------
__global__ void sqnorm_kernel() {
    const int row = blockIdx.x, tid = threadIdx.x;
    __shared__ float sh[4];
    const float* xr = d_x + (size_t)row * HD;
    float4 v = *(const float4*)(xr + tid * 4);
    float s = v.x * v.x + v.y * v.y + v.z * v.z + v.w * v.w;
    const int lane = tid & 31, w = tid >> 5;
#pragma unroll
    for (int o = 16; o > 0; o >>= 1) s += __shfl_down_sync(0xffffffffu, s, o);
    if (lane == 0) sh[w] = s;
    __syncthreads();
    if (tid == 0) d_sq[row] = sh[0] + sh[1] + sh[2] + sh[3];
}

// ---------------------------------------------------------------------------
// Approx top-KC candidates per row. Warp per row, streaming (.cs) loads.
// ---------------------------------------------------------------------------
__global__ __launch_bounds__(256)
void topk_kernel() {
    const int w = threadIdx.x >> 5;
    const int lane = threadIdx.x & 31;
    const int row = blockIdx.x * 8 + w;
    const int b = row >> 11;
    const int i = row & (NI - 1);
    const float4* drow = (const float4*)(d_d2 + (size_t)b * NI * NI + (size_t)i * NI);

    float bd[KC]; int bix[KC];
#pragma unroll
    for (int k = 0; k < KC; k++) { bd[k] = 3.4e38f; bix[k] = 0x7fffffff; }

    for (int j0 = lane * 8; j0 < NI; j0 += 256) {
        float4 da = __ldcs(drow + (j0 >> 2));
        float4 db = __ldcs(drow + (j0 >> 2) + 1);
        float vs[8] = {da.x, da.y, da.z, da.w, db.x, db.y, db.z, db.w};
#pragma unroll
        for (int t = 0; t < 8; t++) {
            float v = vs[t];
            if (v < bd[KC - 1]) {
                bd[KC - 1] = v; bix[KC - 1] = j0 + t;
#pragma unroll
                for (int q = KC - 1; q > 0; q--) {
                    if (bd[q] < bd[q - 1]) {
                        float tf = bd[q]; bd[q] = bd[q - 1]; bd[q - 1] = tf;
                        int ti = bix[q]; bix[q] = bix[q - 1]; bix[q - 1] = ti;
                    }
                }
            }
        }
    }

    int* oc = d_cand + (size_t)row * KC;
    int cp = 0;
    float cv = bd[0]; int ci = bix[0];
#pragma unroll
    for (int k = 0; k < KC; k++) {
        float rv = cv; int ri = ci;
#pragma unroll
        for (int off = 16; off > 0; off >>= 1) {
            float ov = __shfl_xor_sync(0xffffffffu, rv, off);
            int   oj = __shfl_xor_sync(0xffffffffu, ri, off);
            if (ov < rv || (ov == rv && oj < ri)) { rv = ov; ri = oj; }
        }
        if (lane == 0) oc[k] = ri;
        if (cv == rv && ci == ri) {
            cp++;
            float nv = 3.4e38f; int ni2 = 0x7fffffff;
#pragma unroll
            for (int q = 1; q < KC; q++) if (cp == q) { nv = bd[q]; ni2 = bix[q]; }
            cv = nv; ci = ni2;
        }
    }
}

// ---------------------------------------------------------------------------
// Exact fp32 re-rank of KC candidates -> true top-KN.
// ---------------------------------------------------------------------------
__global__ void rerank_kernel() {
    const int row = blockIdx.x;
    const int b = row >> 11;
    const int wid = threadIdx.x >> 5, lane = threadIdx.x & 31;
    __shared__ float sval[KC];
    __shared__ int   sidx[KC];

    if (wid < KC) {
        const int j = d_cand[(size_t)row * KC + wid];
        const float* xi = d_x + (size_t)row * HD;
        const float* xj = d_x + (size_t)(b * NI + j) * HD;
        float acc = 0.f;
#pragma unroll
        for (int t = 0; t < 4; t++) {
            float4 a = *(const float4*)(xi + (lane + t * 32) * 4);
            float4 c = *(const float4*)(xj + (lane + t * 32) * 4);
            acc += a.x * c.x + a.y * c.y + a.z * c.z + a.w * c.w;
        }
#pragma unroll
        for (int o = 16; o > 0; o >>= 1) acc += __shfl_down_sync(0xffffffffu, acc, o);
        if (lane == 0) {
            sval[wid] = d_sq[b * NI + j] - 2.f * acc;
            sidx[wid] = j;
        }
    }
    __syncthreads();
    if (threadIdx.x == 0) {
        int* oi = d_idx + (size_t)row * KN;
        bool used[KC];
#pragma unroll
        for (int k = 0; k < KC; k++) used[k] = false;
#pragma unroll
        for (int k = 0; k < KN; k++) {
            float best = 3.5e38f; int bi = 0x7fffffff; int bp = 0;
#pragma unroll
            for (int t = 0; t < KC; t++) {
                if (!used[t]) {
                    float v = sval[t]; int ii = sidx[t];
                    if (v < best || (v == best && ii < bi)) { best = v; bi = ii; bp = t; }
                }
            }
            used[bp] = true;
            oi[k] = bi;
        }
    }
}

// ---------------------------------------------------------------------------
// EdgeConv: g[row,h] = max_k relu(P - Q + b_g + Q[nbr_k])
// ---------------------------------------------------------------------------
__global__ void edgeconv_kernel(const float* __restrict__ bgv) {
    const int row = blockIdx.x;
    const int b = row >> 11;
    const int tid = threadIdx.x;
    __shared__ int sj[KN];
    if (tid < KN) sj[tid] = d_idx[(size_t)row * KN + tid];
    __syncthreads();
    const int hh = tid * 4;
    float4 p  = *(const float4*)(d_P + (size_t)row * HD + hh);
    float4 q  = *(const float4*)(d_Q + (size_t)row * HD + hh);
    float4 bg = *(const float4*)(bgv + hh);
    float bx_ = p.x - q.x + bg.x;
    float by_ = p.y - q.y + bg.y;
    float bz_ = p.z - q.z + bg.z;
    float bw_ = p.w - q.w + bg.w;
    float mx = 0.f, my = 0.f, mz = 0.f, mw = 0.f;
    const float* Qb = d_Q + (size_t)b * NI * HD;
#pragma unroll
    for (int k = 0; k < KN; k++) {
        float4 qk = *(const float4*)(Qb + (size_t)sj[k] * HD + hh);
        mx = fmaxf(mx, bx_ + qk.x);
        my = fmaxf(my, by_ + qk.y);
        mz = fmaxf(mz, bz_ + qk.z);
        mw = fmaxf(mw, bw_ + qk.w);
    }
    float4 o; o.x = mx; o.y = my; o.z = mz; o.w = mw;
    *(float4*)(d_g + (size_t)row * HD + hh) = o;
}

__device__ __forceinline__ float blockReduceSum(float v, float* sh) {
    int lane = threadIdx.x & 31, w = threadIdx.x >> 5;
#pragma unroll
    for (int o = 16; o > 0; o >>= 1) v += __shfl_down_sync(0xffffffffu, v, o);
    if (lane == 0) sh[w] = v;
    __syncthreads();
    int nw = blockDim.x >> 5;
    v = (threadIdx.x < nw) ? sh[threadIdx.x] : 0.f;
    if (w == 0)
#pragma unroll
        for (int o = 16; o > 0; o >>= 1) v += __shfl_down_sync(0xffffffffu, v, o);
    return v;
}

// ---------------------------------------------------------------------------
// Gated attention score -> A_raw
// ---------------------------------------------------------------------------
__global__ void gate_kernel(const float* __restrict__ ba, const float* __restrict__ bb,
                            const float* __restrict__ Wc, const float* __restrict__ bc,
                            float* __restrict__ out) {
    const int row = blockIdx.x, tid = threadIdx.x;
    __shared__ float sh[32];
    const float* ap = d_Ap + (size_t)row * DA;
    const float* bp = d_Bp + (size_t)row * DA;
    float s = 0.f;
    for (int dd = tid; dd < DA; dd += 128) {
        float av = tanhf(ap[dd] + ba[dd]);
        float bv = bp[dd] + bb[dd];
        bv = 1.f / (1.f + expf(-bv));
        s += av * bv * Wc[dd];
    }
    s = blockReduceSum(s, sh);
    if (tid == 0) {
        float v = s + bc[0];
        d_Ar[row] = v;
        out[2 * NB * NC + row] = v;
    }
}

// ---------------------------------------------------------------------------
// Per-bag softmax stats; zero d_M.
// ---------------------------------------------------------------------------
__global__ void attn_stats_kernel() {
    const int b = blockIdx.x, tid = threadIdx.x;
    __shared__ float red[512];
    float* Ar = d_Ar + (size_t)b * NI;

    float mx = -3.4e38f;
    for (int n = tid; n < NI; n += 512) mx = fmaxf(mx, Ar[n]);
    red[tid] = mx; __syncthreads();
    for (int s = 256; s > 0; s >>= 1) { if (tid < s) red[tid] = fmaxf(red[tid], red[tid + s]); __syncthreads(); }
    mx = red[0];
    __syncthreads();

    float sum = 0.f;
    for (int n = tid; n < NI; n += 512) sum += expf(Ar[n] - mx);
    red[tid] = sum; __syncthreads();
    for (int s = 256; s > 0; s >>= 1) { if (tid < s) red[tid] += red[tid + s]; __syncthreads(); }
    const float inv = 1.f / red[0];
    __syncthreads();

    for (int n = tid; n < NI; n += 512) Ar[n] = expf(Ar[n] - mx) * inv;
    d_M[b * HD + tid] = 0.f;
}

// ---------------------------------------------------------------------------
// Chunked weighted pooling with atomics
// ---------------------------------------------------------------------------
__global__ void pool_acc_kernel() {
    const int b = blockIdx.x, ch = blockIdx.y, tid = threadIdx.x;
    const float* w  = d_Ar + (size_t)b * NI + ch * 128;
    const float* gb = d_g + ((size_t)b * NI + (size_t)ch * 128) * HD;
    __shared__ float ws[128];
    if (tid < 128) ws[tid] = w[tid];
    __syncthreads();
    const int c0 = tid, c1 = tid + 256;
    float a0 = 0.f, a1 = 0.f;
    for (int n = 0; n < 128; n++) {
        const float wn = ws[n];
        a0 = fmaf(wn, gb[(size_t)n * HD + c0], a0);
        a1 = fmaf(wn, gb[(size_t)n * HD + c1], a1);
    }
    atomicAdd(&d_M[b * HD + c0], a0);
    atomicAdd(&d_M[b * HD + c1], a1);
}

// ---------------------------------------------------------------------------
// Classifier head + Y_prob
// ---------------------------------------------------------------------------
__global__ void head_kernel(const float* __restrict__ Wcls, const float* __restrict__ bcls,
                            float* __restrict__ out) {
    const int b = blockIdx.x, tid = threadIdx.x;
    __shared__ float sh[32];
    float s0 = 0.f, s1 = 0.f;
    for (int hh = tid; hh < HD; hh += 128) {
        float m = d_M[b * HD + hh];
        s0 = fmaf(m, Wcls[hh * NC + 0], s0);
        s1 = fmaf(m, Wcls[hh * NC + 1], s1);
    }
    s0 = blockReduceSum(s0, sh);
    __syncthreads();
    s1 = blockReduceSum(s1, sh);
    if (tid == 0) {
        float l0 = s0 + bcls[0], l1 = s1 + bcls[1];
        out[b * NC + 0] = l0;
        out[b * NC + 1] = l1;
        float mx = fmaxf(l0, l1);
        float e0 = expf(l0 - mx), e1 = expf(l1 - mx);
        float inv = 1.f / (e0 + e1);
        out[NB * NC + b * NC + 0] = e0 * inv;
        out[NB * NC + b * NC + 1] = e1 * inv;
    }
}

// ---------------------------------------------------------------------------
extern "C" void kernel_launch(void* const* d_in, const int* in_sizes, int n_in,
                              void* d_out, int out_size) {
    const float* h     = (const float*)d_in[0];
    const float* W_fc  = (const float*)d_in[1];
    const float* b_fc  = (const float*)d_in[2];
    const float* W_g   = (const float*)d_in[3];
    const float* b_g   = (const float*)d_in[4];
    const float* W_a   = (const float*)d_in[5];
    const float* b_a   = (const float*)d_in[6];
    const float* W_b   = (const float*)d_in[7];
    const float* b_b   = (const float*)d_in[8];
    const float* W_c   = (const float*)d_in[9];
    const float* b_c   = (const float*)d_in[10];
    const float* W_cls = (const float*)d_in[11];
    const float* b_cls = (const float*)d_in[12];
    float* out = (float*)d_out;

    // one-time side stream + events (created on the uncaptured correctness call)
    static cudaStream_t s2 = nullptr;
    static cudaEvent_t evFork = nullptr, evJoin = nullptr;
    static bool inited = false;
    if (!inited) {
        if (cudaStreamCreateWithFlags(&s2, cudaStreamNonBlocking) != cudaSuccess) s2 = nullptr;
        if (s2) {
            if (cudaEventCreateWithFlags(&evFork, cudaEventDisableTiming) != cudaSuccess ||
                cudaEventCreateWithFlags(&evJoin, cudaEventDisableTiming) != cudaSuccess) {
                s2 = nullptr;
            }
        }
        inited = true;
    }

    void *px, *pP, *pQ, *pg, *pAp, *pBp, *pd2;
    cudaGetSymbolAddress(&px, d_x);
    cudaGetSymbolAddress(&pP, d_P);
    cudaGetSymbolAddress(&pQ, d_Q);
    cudaGetSymbolAddress(&pg, d_g);
    cudaGetSymbolAddress(&pAp, d_Ap);
    cudaGetSymbolAddress(&pBp, d_Bp);
    cudaGetSymbolAddress(&pd2, d_d2);
    float* x  = (float*)px;
    float* P  = (float*)pP;
    float* Q  = (float*)pQ;
    float* g  = (float*)pg;
    float* Ap = (float*)pAp;
    float* Bp = (float*)pBp;
    float* d2 = (float*)pd2;

    const int NT = NI / XBN;   // 16

    // 1. x = relu(h @ W_fc + b_fc)  — fp32 FFMA exact (kNN-critical)
    gemm_f32_relu<<<dim3(HD / FBN, MROWS / FBM), 256>>>(h, W_fc, b_fc, x, MROWS, DIM, HD);
    // 2. squared norms
    sqnorm_kernel<<<MROWS, 128>>>();

    if (s2) {
        // fork: side stream runs Gram -> topk -> rerank
        cudaEventRecord(evFork, 0);
        cudaStreamWaitEvent(s2, evFork, 0);
        gemm_bf<2, 1><<<dim3(NT, NT, NB), 256, 0, s2>>>(x, nullptr, nullptr, d2, nullptr, NI, HD, NI);
        topk_kernel<<<MROWS / 8, 256, 0, s2>>>();
        rerank_kernel<<<MROWS, KC * 32, 0, s2>>>();
        cudaEventRecord(evJoin, s2);
        // main stream: P and Q (fused z-launch) in parallel
        gemm_bf<0, 0><<<dim3(HD / XBN, MROWS / XBM, 2), 256>>>(
            x, W_g, W_g + (size_t)HD * HD, P, Q, MROWS, HD, HD);
        cudaStreamWaitEvent(0, evJoin, 0);
    } else {
        gemm_bf<2, 1><<<dim3(NT, NT, NB), 256>>>(x, nullptr, nullptr, d2, nullptr, NI, HD, NI);
        topk_kernel<<<MROWS / 8, 256>>>();
        rerank_kernel<<<MROWS, KC * 32>>>();
        gemm_bf<0, 0><<<dim3(HD / XBN, MROWS / XBM, 2), 256>>>(
            x, W_g, W_g + (size_t)HD * HD, P, Q, MROWS, HD, HD);
    }

    // 7. edgeconv gather + max (b_g added here)
    edgeconv_kernel<<<MROWS, 128>>>(b_g);
    // 8/9. attention pre-projections (fused z-launch; biases in gate)
    gemm_bf<0, 0><<<dim3(DA / XBN, MROWS / XBM, 2), 256>>>(
        g, W_a, W_b, Ap, Bp, MROWS, HD, DA);
    // 10. gated attention score -> A_raw
    gate_kernel<<<MROWS, 128>>>(b_a, b_b, W_c, b_c, out);
    // 11. softmax stats + zero M
    attn_stats_kernel<<<NB, 512>>>();
    // 12. chunked weighted pooling
    pool_acc_kernel<<<dim3(NB, 16), 256>>>();
    // 13. classifier head + Y_prob
    head_kernel<<<NB, 128>>>(W_cls, b_cls, out);
}

// round 15
// speedup vs baseline: 1.9328x; 1.0237x over previous
#include <cuda_runtime.h>
#include <cuda_bf16.h>
#include <math.h>
#include <cstdint>

constexpr int NB  = 8;
constexpr int NI  = 2048;
constexpr int DIM = 1024;
constexpr int HD  = 512;
constexpr int DA  = 256;
constexpr int KN  = 5;
constexpr int KC  = 9;      // candidates for exact re-rank
constexpr int NC  = 2;
constexpr int MROWS = NB * NI;   // 16384

// Scratch (static device globals)
__device__ float d_x [MROWS * HD];
__device__ float d_sq[MROWS];
__device__ float d_d2[(size_t)NB * NI * NI];   // 128 MB
__device__ int   d_cand[MROWS * KC];
__device__ int   d_idx[MROWS * KN];
__device__ float d_P [MROWS * HD];
__device__ float d_Q [MROWS * HD];
__device__ float d_g [MROWS * HD];
__device__ float d_Ap[MROWS * DA];
__device__ float d_Bp[MROWS * DA];
__device__ float d_Ar[MROWS];
__device__ float d_M [NB * HD];

// ===========================================================================
// PART 1: fp32 FFMA GEMM (exact) — fc layer only (kNN-critical x).
// ===========================================================================
constexpr int FBM = 128, FBN = 128, FBK = 8;

__global__ __launch_bounds__(256, 2)
void gemm_f32_relu(const float* __restrict__ A, const float* __restrict__ Bm,
                   const float* __restrict__ bias, float* __restrict__ Cm,
                   int M, int Kd, int Nd) {
    __shared__ float As[2][FBK][FBM];
    __shared__ float Bs[2][FBK][FBN];
    const int tid = threadIdx.x;
    const int tx = tid & 15, ty = tid >> 4;
    const int rowBase = blockIdx.y * FBM;
    const int colBase = blockIdx.x * FBN;
    const int arow = tid >> 1, acol = (tid & 1) * 4;
    const int brow = tid >> 5, bcol = (tid & 31) * 4;

    float4 aR = *(const float4*)(A + (size_t)(rowBase + arow) * Kd + acol);
    float4 bR = *(const float4*)(Bm + (size_t)brow * Nd + colBase + bcol);
    As[0][acol + 0][arow] = aR.x; As[0][acol + 1][arow] = aR.y;
    As[0][acol + 2][arow] = aR.z; As[0][acol + 3][arow] = aR.w;
    *(float4*)&Bs[0][brow][bcol] = bR;
    __syncthreads();

    float acc[8][8];
#pragma unroll
    for (int m = 0; m < 8; m++)
#pragma unroll
        for (int n = 0; n < 8; n++) acc[m][n] = 0.f;

    const int KT = Kd / FBK;
    for (int kt = 0; kt < KT; kt++) {
        const int cur = kt & 1;
        if (kt + 1 < KT) {
            const int k0 = (kt + 1) * FBK;
            aR = *(const float4*)(A + (size_t)(rowBase + arow) * Kd + k0 + acol);
            bR = *(const float4*)(Bm + (size_t)(k0 + brow) * Nd + colBase + bcol);
        }
#pragma unroll
        for (int kk = 0; kk < FBK; kk++) {
            float4 a0 = *(const float4*)&As[cur][kk][ty * 4];
            float4 a1 = *(const float4*)&As[cur][kk][64 + ty * 4];
            float4 b0 = *(const float4*)&Bs[cur][kk][tx * 4];
            float4 b1 = *(const float4*)&Bs[cur][kk][64 + tx * 4];
            float av[8] = {a0.x, a0.y, a0.z, a0.w, a1.x, a1.y, a1.z, a1.w};
            float bv[8] = {b0.x, b0.y, b0.z, b0.w, b1.x, b1.y, b1.z, b1.w};
#pragma unroll
            for (int m = 0; m < 8; m++)
#pragma unroll
                for (int n = 0; n < 8; n++)
                    acc[m][n] = fmaf(av[m], bv[n], acc[m][n]);
        }
        if (kt + 1 < KT) {
            const int nxt = cur ^ 1;
            As[nxt][acol + 0][arow] = aR.x; As[nxt][acol + 1][arow] = aR.y;
            As[nxt][acol + 2][arow] = aR.z; As[nxt][acol + 3][arow] = aR.w;
            *(float4*)&Bs[nxt][brow][bcol] = bR;
            __syncthreads();
        }
    }

#pragma unroll
    for (int m = 0; m < 8; m++) {
        const int r = rowBase + ((m < 4) ? (ty * 4 + m) : (64 + ty * 4 + (m - 4)));
        const int c0 = colBase + tx * 4;
        const int c1 = colBase + 64 + tx * 4;
        float4 t0 = *(const float4*)&bias[c0];
        float4 t1 = *(const float4*)&bias[c1];
        float4 v0, v1;
        v0.x = fmaxf(acc[m][0] + t0.x, 0.f); v0.y = fmaxf(acc[m][1] + t0.y, 0.f);
        v0.z = fmaxf(acc[m][2] + t0.z, 0.f); v0.w = fmaxf(acc[m][3] + t0.w, 0.f);
        v1.x = fmaxf(acc[m][4] + t1.x, 0.f); v1.y = fmaxf(acc[m][5] + t1.y, 0.f);
        v1.z = fmaxf(acc[m][6] + t1.z, 0.f); v1.w = fmaxf(acc[m][7] + t1.w, 0.f);
        *(float4*)&Cm[(size_t)r * Nd + c0] = v0;
        *(float4*)&Cm[(size_t)r * Nd + c1] = v1;
    }
}

// ===========================================================================
// PART 2: bf16-3x GEMM (inline split).
// EPI 0: plain A@B, grid.z selects (B0,C0)/(B1,C1). EPI 2: Gram -> d2 + mirror.
// TRB: B row-major [Nd x Kd].
// ===========================================================================
constexpr int XBM = 128, XBN = 128, XBK = 16;
constexpr int LDW = 136;
constexpr int ARR = 8 * LDW;

__device__ __forceinline__ uint32_t pack_hi(float a, float b, float& la, float& lb) {
    __nv_bfloat16 ha = __float2bfloat16_rn(a);
    __nv_bfloat16 hb = __float2bfloat16_rn(b);
    la = a - __bfloat162float(ha);
    lb = b - __bfloat162float(hb);
    return ((uint32_t)__bfloat16_as_ushort(hb) << 16) | __bfloat16_as_ushort(ha);
}
__device__ __forceinline__ uint32_t pack_lo(float la, float lb) {
    __nv_bfloat162 t = __floats2bfloat162_rn(la, lb);
    return *(uint32_t*)&t;
}
__device__ __forceinline__ void mma_bf16(float* c, uint32_t a0, uint32_t a1,
                                         uint32_t a2, uint32_t a3,
                                         uint32_t b0, uint32_t b1) {
    asm volatile(
        "mma.sync.aligned.m16n8k16.row.col.f32.bf16.bf16.f32 "
        "{%0,%1,%2,%3}, {%4,%5,%6,%7}, {%8,%9}, {%0,%1,%2,%3};\n"
        : "+f"(c[0]), "+f"(c[1]), "+f"(c[2]), "+f"(c[3])
        : "r"(a0), "r"(a1), "r"(a2), "r"(a3), "r"(b0), "r"(b1));
}

template <int EPI, int TRB>
__global__ __launch_bounds__(256, 2)
void gemm_bf(const float* __restrict__ Aall, const float* __restrict__ B0,
             const float* __restrict__ B1, float* __restrict__ C0,
             float* __restrict__ C1, int M, int Kd, int Nd) {
    const int bx = blockIdx.x, by = blockIdx.y;
    const float* A = Aall;
    const float* B;
    float* C;
    const float* sqb = nullptr;
    if (EPI == 2) {
        if (by > bx) return;
        const int bag = blockIdx.z;
        A = Aall + (size_t)bag * NI * HD;
        B = A;
        C = C0 + (size_t)bag * NI * NI;
        sqb = d_sq + bag * NI;
    } else {
        B = blockIdx.z ? B1 : B0;
        C = blockIdx.z ? C1 : C0;
    }
    const int rowBase = by * XBM, colBase = bx * XBN;

    __shared__ uint32_t S[2][4][ARR];

    const int tid = threadIdx.x;
    const int lane = tid & 31;
    const int grp = lane >> 2;
    const int tig = lane & 3;
    const int warpId = tid >> 5;
    const int wm = (warpId & 1) * 64;
    const int wn = (warpId >> 1) * 32;

    const int sa_row = tid >> 3;
    const int sa_k2  = tid & 7;
    const int sb_k2  = tid >> 5;
    const int sb_n   = (tid & 31) * 4;

    float2 pa[4], pb[4];
    float4 pw0, pw1;

    auto gload = [&](int k0) {
#pragma unroll
        for (int p = 0; p < 4; p++)
            pa[p] = *(const float2*)(A + (size_t)(rowBase + p * 32 + sa_row) * Kd + k0 + sa_k2 * 2);
        if (TRB) {
#pragma unroll
            for (int p = 0; p < 4; p++)
                pb[p] = *(const float2*)(B + (size_t)(colBase + p * 32 + sa_row) * Kd + k0 + sa_k2 * 2);
        } else {
            const int k = k0 + sb_k2 * 2;
            pw0 = *(const float4*)(B + (size_t)k * Nd + colBase + sb_n);
            pw1 = *(const float4*)(B + (size_t)(k + 1) * Nd + colBase + sb_n);
        }
    };
    auto sstore = [&](int buf) {
#pragma unroll
        for (int p = 0; p < 4; p++) {
            const int row = p * 32 + sa_row;
            float la, lb;
            uint32_t h = pack_hi(pa[p].x, pa[p].y, la, lb);
            S[buf][0][sa_k2 * LDW + row] = h;
            S[buf][1][sa_k2 * LDW + row] = pack_lo(la, lb);
        }
        if (TRB) {
#pragma unroll
            for (int p = 0; p < 4; p++) {
                const int n = p * 32 + sa_row;
                float la, lb;
                uint32_t h = pack_hi(pb[p].x, pb[p].y, la, lb);
                S[buf][2][sa_k2 * LDW + n] = h;
                S[buf][3][sa_k2 * LDW + n] = pack_lo(la, lb);
            }
        } else {
            float l0, l1, l2, l3, l4, l5, l6, l7;
            uint32_t h0 = pack_hi(pw0.x, pw1.x, l0, l1);
            uint32_t h1 = pack_hi(pw0.y, pw1.y, l2, l3);
            uint32_t h2 = pack_hi(pw0.z, pw1.z, l4, l5);
            uint32_t h3 = pack_hi(pw0.w, pw1.w, l6, l7);
            *(uint4*)&S[buf][2][sb_k2 * LDW + sb_n] = make_uint4(h0, h1, h2, h3);
            *(uint4*)&S[buf][3][sb_k2 * LDW + sb_n] =
                make_uint4(pack_lo(l0, l1), pack_lo(l2, l3), pack_lo(l4, l5), pack_lo(l6, l7));
        }
    };

    gload(0);
    sstore(0);
    __syncthreads();

    float acc[4][4][4];
#pragma unroll
    for (int mi = 0; mi < 4; mi++)
#pragma unroll
        for (int ni = 0; ni < 4; ni++)
#pragma unroll
            for (int q = 0; q < 4; q++) acc[mi][ni][q] = 0.f;

    const int KT = Kd / XBK;
    for (int kt = 0; kt < KT; kt++) {
        const int cur = kt & 1;
        if (kt + 1 < KT) gload((kt + 1) * XBK);

        uint32_t bhi[4][2], blo[4][2];
#pragma unroll
        for (int ni = 0; ni < 4; ni++) {
            const int n = wn + ni * 8 + grp;
            bhi[ni][0] = S[cur][2][tig * LDW + n];
            bhi[ni][1] = S[cur][2][(tig + 4) * LDW + n];
            blo[ni][0] = S[cur][3][tig * LDW + n];
            blo[ni][1] = S[cur][3][(tig + 4) * LDW + n];
        }
#pragma unroll
        for (int mi = 0; mi < 4; mi++) {
            const int r = wm + mi * 16 + grp;
            uint32_t ah0 = S[cur][0][tig * LDW + r];
            uint32_t ah1 = S[cur][0][tig * LDW + r + 8];
            uint32_t ah2 = S[cur][0][(tig + 4) * LDW + r];
            uint32_t ah3 = S[cur][0][(tig + 4) * LDW + r + 8];
            uint32_t al0 = S[cur][1][tig * LDW + r];
            uint32_t al1 = S[cur][1][tig * LDW + r + 8];
            uint32_t al2 = S[cur][1][(tig + 4) * LDW + r];
            uint32_t al3 = S[cur][1][(tig + 4) * LDW + r + 8];
#pragma unroll
            for (int ni = 0; ni < 4; ni++) {
                mma_bf16(acc[mi][ni], ah0, ah1, ah2, ah3, bhi[ni][0], bhi[ni][1]);
                mma_bf16(acc[mi][ni], ah0, ah1, ah2, ah3, blo[ni][0], blo[ni][1]);
                mma_bf16(acc[mi][ni], al0, al1, al2, al3, bhi[ni][0], bhi[ni][1]);
            }
        }
        if (kt + 1 < KT) {
            sstore(cur ^ 1);
            __syncthreads();
        }
    }

    // ---- epilogue ----
#pragma unroll
    for (int mi = 0; mi < 4; mi++) {
        const int row = rowBase + wm + mi * 16 + grp;
#pragma unroll
        for (int ni = 0; ni < 4; ni++) {
            const int col = colBase + wn + ni * 8 + tig * 2;
            float c0 = acc[mi][ni][0], c1 = acc[mi][ni][1];
            float c2 = acc[mi][ni][2], c3 = acc[mi][ni][3];
            if (EPI == 2) {
                const float sr0 = sqb[row], sr8 = sqb[row + 8];
                const float sc0 = sqb[col], sc1 = sqb[col + 1];
                float2 v0, v1;
                v0.x = sr0 + sc0 - 2.f * c0;  v0.y = sr0 + sc1 - 2.f * c1;
                v1.x = sr8 + sc0 - 2.f * c2;  v1.y = sr8 + sc1 - 2.f * c3;
                *(float2*)&C[(size_t)row * Nd + col] = v0;
                *(float2*)&C[(size_t)(row + 8) * Nd + col] = v1;
                if (bx != by) {
                    C[(size_t)col * Nd + row]           = v0.x;
                    C[(size_t)col * Nd + row + 8]       = v1.x;
                    C[(size_t)(col + 1) * Nd + row]     = v0.y;
                    C[(size_t)(col + 1) * Nd + row + 8] = v1.y;
                }
            } else {
                float2 v0; v0.x = c0; v0.y = c1;
                float2 v1; v1.x = c2; v1.y = c3;
                *(float2*)&C[(size_t)row * Nd + col] = v0;
                *(float2*)&C[(size_t)(row + 8) * Nd + col] = v1;
            }
        }
    }
}

// ---------------------------------------------------------------------------
// Row squared norms
// ---------------------------------------------------------------------------
__global__ void sqnorm_kernel() {
    const int row = blockIdx.x, tid = threadIdx.x;
    __shared__ float sh[4];
    const float* xr = d_x + (size_t)row * HD;
    float4 v = *(const float4*)(xr + tid * 4);
    float s = v.x * v.x + v.y * v.y + v.z * v.z + v.w * v.w;
    const int lane = tid & 31, w = tid >> 5;
#pragma unroll
    for (int o = 16; o > 0; o >>= 1) s += __shfl_down_sync(0xffffffffu, s, o);
    if (lane == 0) sh[w] = s;
    __syncthreads();
    if (tid == 0) d_sq[row] = sh[0] + sh[1] + sh[2] + sh[3];
}

// ---------------------------------------------------------------------------
// Approx top-KC: TWO warps per row (1024 cols each), then per-row 2*KC merge.
// 256 threads = 8 warps = 4 rows. (val,idx) lexicographic tie-break throughout.
// ---------------------------------------------------------------------------
__global__ __launch_bounds__(256)
void topk_kernel() {
    const int warpId = threadIdx.x >> 5;
    const int lane = threadIdx.x & 31;
    const int rloc = warpId >> 1;         // 0..3
    const int half = warpId & 1;          // 0..1
    const int row = blockIdx.x * 4 + rloc;
    const int b = row >> 11;
    const int i = row & (NI - 1);
    const float4* drow = (const float4*)(d_d2 + (size_t)b * NI * NI + (size_t)i * NI);

    __shared__ float sv[4][2 * KC];
    __shared__ int   si[4][2 * KC];

    float bd[KC]; int bix[KC];
#pragma unroll
    for (int k = 0; k < KC; k++) { bd[k] = 3.4e38f; bix[k] = 0x7fffffff; }

    const int base = half * (NI / 2);
#pragma unroll
    for (int it = 0; it < 4; it++) {
        const int j0 = base + it * 256 + lane * 8;
        float4 da = __ldcs(drow + (j0 >> 2));
        float4 db = __ldcs(drow + (j0 >> 2) + 1);
        float vs[8] = {da.x, da.y, da.z, da.w, db.x, db.y, db.z, db.w};
#pragma unroll
        for (int t = 0; t < 8; t++) {
            float v = vs[t];
            if (v < bd[KC - 1]) {
                bd[KC - 1] = v; bix[KC - 1] = j0 + t;
#pragma unroll
                for (int q = KC - 1; q > 0; q--) {
                    if (bd[q] < bd[q - 1]) {
                        float tf = bd[q]; bd[q] = bd[q - 1]; bd[q - 1] = tf;
                        int ti = bix[q]; bix[q] = bix[q - 1]; bix[q - 1] = ti;
                    }
                }
            }
        }
    }

    // per-warp merge -> sorted KC into smem
    {
        int cp = 0;
        float cv = bd[0]; int ci = bix[0];
#pragma unroll
        for (int k = 0; k < KC; k++) {
            float rv = cv; int ri = ci;
#pragma unroll
            for (int off = 16; off > 0; off >>= 1) {
                float ov = __shfl_xor_sync(0xffffffffu, rv, off);
                int   oj = __shfl_xor_sync(0xffffffffu, ri, off);
                if (ov < rv || (ov == rv && oj < ri)) { rv = ov; ri = oj; }
            }
            if (lane == 0) { sv[rloc][half * KC + k] = rv; si[rloc][half * KC + k] = ri; }
            if (cv == rv && ci == ri) {
                cp++;
                float nv = 3.4e38f; int ni2 = 0x7fffffff;
#pragma unroll
                for (int q = 1; q < KC; q++) if (cp == q) { nv = bd[q]; ni2 = bix[q]; }
                cv = nv; ci = ni2;
            }
        }
    }
    __syncthreads();

    // final merge (even warps): 2*KC=18 candidates in lanes, KC argmin rounds
    if (half == 0) {
        float mv = 3.4e38f; int mi = 0x7fffffff;
        if (lane < 2 * KC) { mv = sv[rloc][lane]; mi = si[rloc][lane]; }
        int* oc = d_cand + (size_t)row * KC;
#pragma unroll
        for (int k = 0; k < KC; k++) {
            float rv = mv; int ri = mi;
#pragma unroll
            for (int off = 16; off > 0; off >>= 1) {
                float ov = __shfl_xor_sync(0xffffffffu, rv, off);
                int   oj = __shfl_xor_sync(0xffffffffu, ri, off);
                if (ov < rv || (ov == rv && oj < ri)) { rv = ov; ri = oj; }
            }
            if (lane == 0) oc[k] = ri;
            if (mv == rv && mi == ri) { mv = 3.4e38f; mi = 0x7fffffff; }
        }
    }
}

// ---------------------------------------------------------------------------
// Exact fp32 re-rank of KC candidates -> true top-KN.
// ---------------------------------------------------------------------------
__global__ void rerank_kernel() {
    const int row = blockIdx.x;
    const int b = row >> 11;
    const int wid = threadIdx.x >> 5, lane = threadIdx.x & 31;
    __shared__ float sval[KC];
    __shared__ int   sidx[KC];

    if (wid < KC) {
        const int j = d_cand[(size_t)row * KC + wid];
        const float* xi = d_x + (size_t)row * HD;
        const float* xj = d_x + (size_t)(b * NI + j) * HD;
        float acc = 0.f;
#pragma unroll
        for (int t = 0; t < 4; t++) {
            float4 a = *(const float4*)(xi + (lane + t * 32) * 4);
            float4 c = *(const float4*)(xj + (lane + t * 32) * 4);
            acc += a.x * c.x + a.y * c.y + a.z * c.z + a.w * c.w;
        }
#pragma unroll
        for (int o = 16; o > 0; o >>= 1) acc += __shfl_down_sync(0xffffffffu, acc, o);
        if (lane == 0) {
            sval[wid] = d_sq[b * NI + j] - 2.f * acc;
            sidx[wid] = j;
        }
    }
    __syncthreads();
    if (threadIdx.x == 0) {
        int* oi = d_idx + (size_t)row * KN;
        bool used[KC];
#pragma unroll
        for (int k = 0; k < KC; k++) used[k] = false;
#pragma unroll
        for (int k = 0; k < KN; k++) {
            float best = 3.5e38f; int bi = 0x7fffffff; int bp = 0;
#pragma unroll
            for (int t = 0; t < KC; t++) {
                if (!used[t]) {
                    float v = sval[t]; int ii = sidx[t];
                    if (v < best || (v == best && ii < bi)) { best = v; bi = ii; bp = t; }
                }
            }
            used[bp] = true;
            oi[k] = bi;
        }
    }
}

// ---------------------------------------------------------------------------
// EdgeConv: g[row,h] = max_k relu(P - Q + b_g + Q[nbr_k])
// ---------------------------------------------------------------------------
__global__ void edgeconv_kernel(const float* __restrict__ bgv) {
    const int row = blockIdx.x;
    const int b = row >> 11;
    const int tid = threadIdx.x;
    __shared__ int sj[KN];
    if (tid < KN) sj[tid] = d_idx[(size_t)row * KN + tid];
    __syncthreads();
    const int hh = tid * 4;
    float4 p  = *(const float4*)(d_P + (size_t)row * HD + hh);
    float4 q  = *(const float4*)(d_Q + (size_t)row * HD + hh);
    float4 bg = *(const float4*)(bgv + hh);
    float bx_ = p.x - q.x + bg.x;
    float by_ = p.y - q.y + bg.y;
    float bz_ = p.z - q.z + bg.z;
    float bw_ = p.w - q.w + bg.w;
    float mx = 0.f, my = 0.f, mz = 0.f, mw = 0.f;
    const float* Qb = d_Q + (size_t)b * NI * HD;
#pragma unroll
    for (int k = 0; k < KN; k++) {
        float4 qk = *(const float4*)(Qb + (size_t)sj[k] * HD + hh);
        mx = fmaxf(mx, bx_ + qk.x);
        my = fmaxf(my, by_ + qk.y);
        mz = fmaxf(mz, bz_ + qk.z);
        mw = fmaxf(mw, bw_ + qk.w);
    }
    float4 o; o.x = mx; o.y = my; o.z = mz; o.w = mw;
    *(float4*)(d_g + (size_t)row * HD + hh) = o;
}

__device__ __forceinline__ float blockReduceSum(float v, float* sh) {
    int lane = threadIdx.x & 31, w = threadIdx.x >> 5;
#pragma unroll
    for (int o = 16; o > 0; o >>= 1) v += __shfl_down_sync(0xffffffffu, v, o);
    if (lane == 0) sh[w] = v;
    __syncthreads();
    int nw = blockDim.x >> 5;
    v = (threadIdx.x < nw) ? sh[threadIdx.x] : 0.f;
    if (w == 0)
#pragma unroll
        for (int o = 16; o > 0; o >>= 1) v += __shfl_down_sync(0xffffffffu, v, o);
    return v;
}

// ---------------------------------------------------------------------------
// Gated attention score -> A_raw
// ---------------------------------------------------------------------------
__global__ void gate_kernel(const float* __restrict__ ba, const float* __restrict__ bb,
                            const float* __restrict__ Wc, const float* __restrict__ bc,
                            float* __restrict__ out) {
    const int row = blockIdx.x, tid = threadIdx.x;
    __shared__ float sh[32];
    const float* ap = d_Ap + (size_t)row * DA;
    const float* bp = d_Bp + (size_t)row * DA;
    float s = 0.f;
    for (int dd = tid; dd < DA; dd += 128) {
        float av = tanhf(ap[dd] + ba[dd]);
        float bv = bp[dd] + bb[dd];
        bv = 1.f / (1.f + expf(-bv));
        s += av * bv * Wc[dd];
    }
    s = blockReduceSum(s, sh);
    if (tid == 0) {
        float v = s + bc[0];
        d_Ar[row] = v;
        out[2 * NB * NC + row] = v;
    }
}

// ---------------------------------------------------------------------------
// Per-bag softmax stats; zero d_M.
// ---------------------------------------------------------------------------
__global__ void attn_stats_kernel() {
    const int b = blockIdx.x, tid = threadIdx.x;
    __shared__ float red[512];
    float* Ar = d_Ar + (size_t)b * NI;

    float mx = -3.4e38f;
    for (int n = tid; n < NI; n += 512) mx = fmaxf(mx, Ar[n]);
    red[tid] = mx; __syncthreads();
    for (int s = 256; s > 0; s >>= 1) { if (tid < s) red[tid] = fmaxf(red[tid], red[tid + s]); __syncthreads(); }
    mx = red[0];
    __syncthreads();

    float sum = 0.f;
    for (int n = tid; n < NI; n += 512) sum += expf(Ar[n] - mx);
    red[tid] = sum; __syncthreads();
    for (int s = 256; s > 0; s >>= 1) { if (tid < s) red[tid] += red[tid + s]; __syncthreads(); }
    const float inv = 1.f / red[0];
    __syncthreads();

    for (int n = tid; n < NI; n += 512) Ar[n] = expf(Ar[n] - mx) * inv;
    d_M[b * HD + tid] = 0.f;
}

// ---------------------------------------------------------------------------
// Chunked weighted pooling with atomics
// ---------------------------------------------------------------------------
__global__ void pool_acc_kernel() {
    const int b = blockIdx.x, ch = blockIdx.y, tid = threadIdx.x;
    const float* w  = d_Ar + (size_t)b * NI + ch * 128;
    const float* gb = d_g + ((size_t)b * NI + (size_t)ch * 128) * HD;
    __shared__ float ws[128];
    if (tid < 128) ws[tid] = w[tid];
    __syncthreads();
    const int c0 = tid, c1 = tid + 256;
    float a0 = 0.f, a1 = 0.f;
    for (int n = 0; n < 128; n++) {
        const float wn = ws[n];
        a0 = fmaf(wn, gb[(size_t)n * HD + c0], a0);
        a1 = fmaf(wn, gb[(size_t)n * HD + c1], a1);
    }
    atomicAdd(&d_M[b * HD + c0], a0);
    atomicAdd(&d_M[b * HD + c1], a1);
}

// ---------------------------------------------------------------------------
// Classifier head + Y_prob
// ---------------------------------------------------------------------------
__global__ void head_kernel(const float* __restrict__ Wcls, const float* __restrict__ bcls,
                            float* __restrict__ out) {
    const int b = blockIdx.x, tid = threadIdx.x;
    __shared__ float sh[32];
    float s0 = 0.f, s1 = 0.f;
    for (int hh = tid; hh < HD; hh += 128) {
        float m = d_M[b * HD + hh];
        s0 = fmaf(m, Wcls[hh * NC + 0], s0);
        s1 = fmaf(m, Wcls[hh * NC + 1], s1);
    }
    s0 = blockReduceSum(s0, sh);
    __syncthreads();
    s1 = blockReduceSum(s1, sh);
    if (tid == 0) {
        float l0 = s0 + bcls[0], l1 = s1 + bcls[1];
        out[b * NC + 0] = l0;
        out[b * NC + 1] = l1;
        float mx = fmaxf(l0, l1);
        float e0 = expf(l0 - mx), e1 = expf(l1 - mx);
        float inv = 1.f / (e0 + e1);
        out[NB * NC + b * NC + 0] = e0 * inv;
        out[NB * NC + b * NC + 1] = e1 * inv;
    }
}

// ---------------------------------------------------------------------------
extern "C" void kernel_launch(void* const* d_in, const int* in_sizes, int n_in,
                              void* d_out, int out_size) {
    const float* h     = (const float*)d_in[0];
    const float* W_fc  = (const float*)d_in[1];
    const float* b_fc  = (const float*)d_in[2];
    const float* W_g   = (const float*)d_in[3];
    const float* b_g   = (const float*)d_in[4];
    const float* W_a   = (const float*)d_in[5];
    const float* b_a   = (const float*)d_in[6];
    const float* W_b   = (const float*)d_in[7];
    const float* b_b   = (const float*)d_in[8];
    const float* W_c   = (const float*)d_in[9];
    const float* b_c   = (const float*)d_in[10];
    const float* W_cls = (const float*)d_in[11];
    const float* b_cls = (const float*)d_in[12];
    float* out = (float*)d_out;

    // one-time side stream + events (created on the uncaptured correctness call)
    static cudaStream_t s2 = nullptr;
    static cudaEvent_t evFork = nullptr, evJoin = nullptr;
    static bool inited = false;
    if (!inited) {
        if (cudaStreamCreateWithFlags(&s2, cudaStreamNonBlocking) != cudaSuccess) s2 = nullptr;
        if (s2) {
            if (cudaEventCreateWithFlags(&evFork, cudaEventDisableTiming) != cudaSuccess ||
                cudaEventCreateWithFlags(&evJoin, cudaEventDisableTiming) != cudaSuccess) {
                s2 = nullptr;
            }
        }
        inited = true;
    }

    void *px, *pP, *pQ, *pg, *pAp, *pBp, *pd2;
    cudaGetSymbolAddress(&px, d_x);
    cudaGetSymbolAddress(&pP, d_P);
    cudaGetSymbolAddress(&pQ, d_Q);
    cudaGetSymbolAddress(&pg, d_g);
    cudaGetSymbolAddress(&pAp, d_Ap);
    cudaGetSymbolAddress(&pBp, d_Bp);
    cudaGetSymbolAddress(&pd2, d_d2);
    float* x  = (float*)px;
    float* P  = (float*)pP;
    float* Q  = (float*)pQ;
    float* g  = (float*)pg;
    float* Ap = (float*)pAp;
    float* Bp = (float*)pBp;
    float* d2 = (float*)pd2;

    const int NT = NI / XBN;   // 16

    // 1. x = relu(h @ W_fc + b_fc)  — fp32 FFMA exact (kNN-critical)
    gemm_f32_relu<<<dim3(HD / FBN, MROWS / FBM), 256>>>(h, W_fc, b_fc, x, MROWS, DIM, HD);
    // 2. squared norms
    sqnorm_kernel<<<MROWS, 128>>>();

    if (s2) {
        // fork: side stream runs Gram -> topk -> rerank
        cudaEventRecord(evFork, 0);
        cudaStreamWaitEvent(s2, evFork, 0);
        gemm_bf<2, 1><<<dim3(NT, NT, NB), 256, 0, s2>>>(x, nullptr, nullptr, d2, nullptr, NI, HD, NI);
        topk_kernel<<<MROWS / 4, 256, 0, s2>>>();
        rerank_kernel<<<MROWS, KC * 32, 0, s2>>>();
        cudaEventRecord(evJoin, s2);
        // main stream: P and Q (fused z-launch) in parallel
        gemm_bf<0, 0><<<dim3(HD / XBN, MROWS / XBM, 2), 256>>>(
            x, W_g, W_g + (size_t)HD * HD, P, Q, MROWS, HD, HD);
        cudaStreamWaitEvent(0, evJoin, 0);
    } else {
        gemm_bf<2, 1><<<dim3(NT, NT, NB), 256>>>(x, nullptr, nullptr, d2, nullptr, NI, HD, NI);
        topk_kernel<<<MROWS / 4, 256>>>();
        rerank_kernel<<<MROWS, KC * 32>>>();
        gemm_bf<0, 0><<<dim3(HD / XBN, MROWS / XBM, 2), 256>>>(
            x, W_g, W_g + (size_t)HD * HD, P, Q, MROWS, HD, HD);
    }

    // 7. edgeconv gather + max (b_g added here)
    edgeconv_kernel<<<MROWS, 128>>>(b_g);
    // 8/9. attention pre-projections (fused z-launch; biases in gate)
    gemm_bf<0, 0><<<dim3(DA / XBN, MROWS / XBM, 2), 256>>>(
        g, W_a, W_b, Ap, Bp, MROWS, HD, DA);
    // 10. gated attention score -> A_raw
    gate_kernel<<<MROWS, 128>>>(b_a, b_b, W_c, b_c, out);
    // 11. softmax stats + zero M
    attn_stats_kernel<<<NB, 512>>>();
    // 12. chunked weighted pooling
    pool_acc_kernel<<<dim3(NB, 16), 256>>>();
    // 13. classifier head + Y_prob
    head_kernel<<<NB, 128>>>(W_cls, b_cls, out);
}

// round 16
// speedup vs baseline: 1.9579x; 1.0130x over previous
#include <cuda_runtime.h>
#include <cuda_bf16.h>
#include <math.h>
#include <cstdint>

constexpr int NB  = 8;
constexpr int NI  = 2048;
constexpr int DIM = 1024;
constexpr int HD  = 512;
constexpr int DA  = 256;
constexpr int KN  = 5;
constexpr int KL  = 5;      // per-lane candidates (provably sufficient)
constexpr int KC  = 9;      // merged candidates for exact re-rank
constexpr int NC  = 2;
constexpr int MROWS = NB * NI;   // 16384

// Scratch (static device globals)
__device__ float d_x [MROWS * HD];
__device__ float d_sq[MROWS];
__device__ float d_d2[(size_t)NB * NI * NI];   // 128 MB
__device__ int   d_cand[MROWS * KC];
__device__ int   d_idx[MROWS * KN];
__device__ float d_P [MROWS * HD];
__device__ float d_Q [MROWS * HD];
__device__ float d_g [MROWS * HD];
__device__ float d_Ap[MROWS * DA];
__device__ float d_Bp[MROWS * DA];
__device__ float d_Ar[MROWS];
__device__ float d_M [NB * HD];

// ===========================================================================
// PART 1: fp32 FFMA GEMM (exact) — fc layer, with FUSED row-sqnorm epilogue.
// Requires d_sq zeroed before launch.
// ===========================================================================
constexpr int FBM = 128, FBN = 128, FBK = 8;

__global__ __launch_bounds__(256, 2)
void gemm_f32_relu(const float* __restrict__ A, const float* __restrict__ Bm,
                   const float* __restrict__ bias, float* __restrict__ Cm,
                   int M, int Kd, int Nd) {
    __shared__ float As[2][FBK][FBM];
    __shared__ float Bs[2][FBK][FBN];
    const int tid = threadIdx.x;
    const int tx = tid & 15, ty = tid >> 4;
    const int rowBase = blockIdx.y * FBM;
    const int colBase = blockIdx.x * FBN;
    const int arow = tid >> 1, acol = (tid & 1) * 4;
    const int brow = tid >> 5, bcol = (tid & 31) * 4;

    float4 aR = *(const float4*)(A + (size_t)(rowBase + arow) * Kd + acol);
    float4 bR = *(const float4*)(Bm + (size_t)brow * Nd + colBase + bcol);
    As[0][acol + 0][arow] = aR.x; As[0][acol + 1][arow] = aR.y;
    As[0][acol + 2][arow] = aR.z; As[0][acol + 3][arow] = aR.w;
    *(float4*)&Bs[0][brow][bcol] = bR;
    __syncthreads();

    float acc[8][8];
#pragma unroll
    for (int m = 0; m < 8; m++)
#pragma unroll
        for (int n = 0; n < 8; n++) acc[m][n] = 0.f;

    const int KT = Kd / FBK;
    for (int kt = 0; kt < KT; kt++) {
        const int cur = kt & 1;
        if (kt + 1 < KT) {
            const int k0 = (kt + 1) * FBK;
            aR = *(const float4*)(A + (size_t)(rowBase + arow) * Kd + k0 + acol);
            bR = *(const float4*)(Bm + (size_t)(k0 + brow) * Nd + colBase + bcol);
        }
#pragma unroll
        for (int kk = 0; kk < FBK; kk++) {
            float4 a0 = *(const float4*)&As[cur][kk][ty * 4];
            float4 a1 = *(const float4*)&As[cur][kk][64 + ty * 4];
            float4 b0 = *(const float4*)&Bs[cur][kk][tx * 4];
            float4 b1 = *(const float4*)&Bs[cur][kk][64 + tx * 4];
            float av[8] = {a0.x, a0.y, a0.z, a0.w, a1.x, a1.y, a1.z, a1.w};
            float bv[8] = {b0.x, b0.y, b0.z, b0.w, b1.x, b1.y, b1.z, b1.w};
#pragma unroll
            for (int m = 0; m < 8; m++)
#pragma unroll
                for (int n = 0; n < 8; n++)
                    acc[m][n] = fmaf(av[m], bv[n], acc[m][n]);
        }
        if (kt + 1 < KT) {
            const int nxt = cur ^ 1;
            As[nxt][acol + 0][arow] = aR.x; As[nxt][acol + 1][arow] = aR.y;
            As[nxt][acol + 2][arow] = aR.z; As[nxt][acol + 3][arow] = aR.w;
            *(float4*)&Bs[nxt][brow][bcol] = bR;
            __syncthreads();
        }
    }

#pragma unroll
    for (int m = 0; m < 8; m++) {
        const int r = rowBase + ((m < 4) ? (ty * 4 + m) : (64 + ty * 4 + (m - 4)));
        const int c0 = colBase + tx * 4;
        const int c1 = colBase + 64 + tx * 4;
        float4 t0 = *(const float4*)&bias[c0];
        float4 t1 = *(const float4*)&bias[c1];
        float4 v0, v1;
        v0.x = fmaxf(acc[m][0] + t0.x, 0.f); v0.y = fmaxf(acc[m][1] + t0.y, 0.f);
        v0.z = fmaxf(acc[m][2] + t0.z, 0.f); v0.w = fmaxf(acc[m][3] + t0.w, 0.f);
        v1.x = fmaxf(acc[m][4] + t1.x, 0.f); v1.y = fmaxf(acc[m][5] + t1.y, 0.f);
        v1.z = fmaxf(acc[m][6] + t1.z, 0.f); v1.w = fmaxf(acc[m][7] + t1.w, 0.f);
        *(float4*)&Cm[(size_t)r * Nd + c0] = v0;
        *(float4*)&Cm[(size_t)r * Nd + c1] = v1;
        // fused sqnorm: 16 threads (one half-warp-of-16) hold row r's 8-col chunks
        float s = v0.x * v0.x + v0.y * v0.y + v0.z * v0.z + v0.w * v0.w
                + v1.x * v1.x + v1.y * v1.y + v1.z * v1.z + v1.w * v1.w;
#pragma unroll
        for (int off = 8; off > 0; off >>= 1)
            s += __shfl_down_sync(0xffffffffu, s, off, 16);
        if (tx == 0) atomicAdd(&d_sq[r], s);
    }
}

// ===========================================================================
// PART 2: bf16-3x GEMM (inline split).
// EPI 0: plain A@B, grid.z selects (B0,C0)/(B1,C1). EPI 2: Gram -> d2 + mirror.
// TRB: B row-major [Nd x Kd].
// ===========================================================================
constexpr int XBM = 128, XBN = 128, XBK = 16;
constexpr int LDW = 136;
constexpr int ARR = 8 * LDW;

__device__ __forceinline__ uint32_t pack_hi(float a, float b, float& la, float& lb) {
    __nv_bfloat16 ha = __float2bfloat16_rn(a);
    __nv_bfloat16 hb = __float2bfloat16_rn(b);
    la = a - __bfloat162float(ha);
    lb = b - __bfloat162float(hb);
    return ((uint32_t)__bfloat16_as_ushort(hb) << 16) | __bfloat16_as_ushort(ha);
}
__device__ __forceinline__ uint32_t pack_lo(float la, float lb) {
    __nv_bfloat162 t = __floats2bfloat162_rn(la, lb);
    return *(uint32_t*)&t;
}
__device__ __forceinline__ void mma_bf16(float* c, uint32_t a0, uint32_t a1,
                                         uint32_t a2, uint32_t a3,
                                         uint32_t b0, uint32_t b1) {
    asm volatile(
        "mma.sync.aligned.m16n8k16.row.col.f32.bf16.bf16.f32 "
        "{%0,%1,%2,%3}, {%4,%5,%6,%7}, {%8,%9}, {%0,%1,%2,%3};\n"
        : "+f"(c[0]), "+f"(c[1]), "+f"(c[2]), "+f"(c[3])
        : "r"(a0), "r"(a1), "r"(a2), "r"(a3), "r"(b0), "r"(b1));
}

template <int EPI, int TRB>
__global__ __launch_bounds__(256, 2)
void gemm_bf(const float* __restrict__ Aall, const float* __restrict__ B0,
             const float* __restrict__ B1, float* __restrict__ C0,
             float* __restrict__ C1, int M, int Kd, int Nd) {
    const int bx = blockIdx.x, by = blockIdx.y;
    const float* A = Aall;
    const float* B;
    float* C;
    const float* sqb = nullptr;
    if (EPI == 2) {
        if (by > bx) return;
        const int bag = blockIdx.z;
        A = Aall + (size_t)bag * NI * HD;
        B = A;
        C = C0 + (size_t)bag * NI * NI;
        sqb = d_sq + bag * NI;
    } else {
        B = blockIdx.z ? B1 : B0;
        C = blockIdx.z ? C1 : C0;
    }
    const int rowBase = by * XBM, colBase = bx * XBN;

    __shared__ uint32_t S[2][4][ARR];

    const int tid = threadIdx.x;
    const int lane = tid & 31;
    const int grp = lane >> 2;
    const int tig = lane & 3;
    const int warpId = tid >> 5;
    const int wm = (warpId & 1) * 64;
    const int wn = (warpId >> 1) * 32;

    const int sa_row = tid >> 3;
    const int sa_k2  = tid & 7;
    const int sb_k2  = tid >> 5;
    const int sb_n   = (tid & 31) * 4;

    float2 pa[4], pb[4];
    float4 pw0, pw1;

    auto gload = [&](int k0) {
#pragma unroll
        for (int p = 0; p < 4; p++)
            pa[p] = *(const float2*)(A + (size_t)(rowBase + p * 32 + sa_row) * Kd + k0 + sa_k2 * 2);
        if (TRB) {
#pragma unroll
            for (int p = 0; p < 4; p++)
                pb[p] = *(const float2*)(B + (size_t)(colBase + p * 32 + sa_row) * Kd + k0 + sa_k2 * 2);
        } else {
            const int k = k0 + sb_k2 * 2;
            pw0 = *(const float4*)(B + (size_t)k * Nd + colBase + sb_n);
            pw1 = *(const float4*)(B + (size_t)(k + 1) * Nd + colBase + sb_n);
        }
    };
    auto sstore = [&](int buf) {
#pragma unroll
        for (int p = 0; p < 4; p++) {
            const int row = p * 32 + sa_row;
            float la, lb;
            uint32_t h = pack_hi(pa[p].x, pa[p].y, la, lb);
            S[buf][0][sa_k2 * LDW + row] = h;
            S[buf][1][sa_k2 * LDW + row] = pack_lo(la, lb);
        }
        if (TRB) {
#pragma unroll
            for (int p = 0; p < 4; p++) {
                const int n = p * 32 + sa_row;
                float la, lb;
                uint32_t h = pack_hi(pb[p].x, pb[p].y, la, lb);
                S[buf][2][sa_k2 * LDW + n] = h;
                S[buf][3][sa_k2 * LDW + n] = pack_lo(la, lb);
            }
        } else {
            float l0, l1, l2, l3, l4, l5, l6, l7;
            uint32_t h0 = pack_hi(pw0.x, pw1.x, l0, l1);
            uint32_t h1 = pack_hi(pw0.y, pw1.y, l2, l3);
            uint32_t h2 = pack_hi(pw0.z, pw1.z, l4, l5);
            uint32_t h3 = pack_hi(pw0.w, pw1.w, l6, l7);
            *(uint4*)&S[buf][2][sb_k2 * LDW + sb_n] = make_uint4(h0, h1, h2, h3);
            *(uint4*)&S[buf][3][sb_k2 * LDW + sb_n] =
                make_uint4(pack_lo(l0, l1), pack_lo(l2, l3), pack_lo(l4, l5), pack_lo(l6, l7));
        }
    };

    gload(0);
    sstore(0);
    __syncthreads();

    float acc[4][4][4];
#pragma unroll
    for (int mi = 0; mi < 4; mi++)
#pragma unroll
        for (int ni = 0; ni < 4; ni++)
#pragma unroll
            for (int q = 0; q < 4; q++) acc[mi][ni][q] = 0.f;

    const int KT = Kd / XBK;
    for (int kt = 0; kt < KT; kt++) {
        const int cur = kt & 1;
        if (kt + 1 < KT) gload((kt + 1) * XBK);

        uint32_t bhi[4][2], blo[4][2];
#pragma unroll
        for (int ni = 0; ni < 4; ni++) {
            const int n = wn + ni * 8 + grp;
            bhi[ni][0] = S[cur][2][tig * LDW + n];
            bhi[ni][1] = S[cur][2][(tig + 4) * LDW + n];
            blo[ni][0] = S[cur][3][tig * LDW + n];
            blo[ni][1] = S[cur][3][(tig + 4) * LDW + n];
        }
#pragma unroll
        for (int mi = 0; mi < 4; mi++) {
            const int r = wm + mi * 16 + grp;
            uint32_t ah0 = S[cur][0][tig * LDW + r];
            uint32_t ah1 = S[cur][0][tig * LDW + r + 8];
            uint32_t ah2 = S[cur][0][(tig + 4) * LDW + r];
            uint32_t ah3 = S[cur][0][(tig + 4) * LDW + r + 8];
            uint32_t al0 = S[cur][1][tig * LDW + r];
            uint32_t al1 = S[cur][1][tig * LDW + r + 8];
            uint32_t al2 = S[cur][1][(tig + 4) * LDW + r];
            uint32_t al3 = S[cur][1][(tig + 4) * LDW + r + 8];
#pragma unroll
            for (int ni = 0; ni < 4; ni++) {
                mma_bf16(acc[mi][ni], ah0, ah1, ah2, ah3, bhi[ni][0], bhi[ni][1]);
                mma_bf16(acc[mi][ni], ah0, ah1, ah2, ah3, blo[ni][0], blo[ni][1]);
                mma_bf16(acc[mi][ni], al0, al1, al2, al3, bhi[ni][0], bhi[ni][1]);
            }
        }
        if (kt + 1 < KT) {
            sstore(cur ^ 1);
            __syncthreads();
        }
    }

    // ---- epilogue ----
#pragma unroll
    for (int mi = 0; mi < 4; mi++) {
        const int row = rowBase + wm + mi * 16 + grp;
#pragma unroll
        for (int ni = 0; ni < 4; ni++) {
            const int col = colBase + wn + ni * 8 + tig * 2;
            float c0 = acc[mi][ni][0], c1 = acc[mi][ni][1];
            float c2 = acc[mi][ni][2], c3 = acc[mi][ni][3];
            if (EPI == 2) {
                const float sr0 = sqb[row], sr8 = sqb[row + 8];
                const float sc0 = sqb[col], sc1 = sqb[col + 1];
                float2 v0, v1;
                v0.x = sr0 + sc0 - 2.f * c0;  v0.y = sr0 + sc1 - 2.f * c1;
                v1.x = sr8 + sc0 - 2.f * c2;  v1.y = sr8 + sc1 - 2.f * c3;
                *(float2*)&C[(size_t)row * Nd + col] = v0;
                *(float2*)&C[(size_t)(row + 8) * Nd + col] = v1;
                if (bx != by) {
                    C[(size_t)col * Nd + row]           = v0.x;
                    C[(size_t)col * Nd + row + 8]       = v1.x;
                    C[(size_t)(col + 1) * Nd + row]     = v0.y;
                    C[(size_t)(col + 1) * Nd + row + 8] = v1.y;
                }
            } else {
                float2 v0; v0.x = c0; v0.y = c1;
                float2 v1; v1.x = c2; v1.y = c3;
                *(float2*)&C[(size_t)row * Nd + col] = v0;
                *(float2*)&C[(size_t)(row + 8) * Nd + col] = v1;
            }
        }
    }
}

// ---------------------------------------------------------------------------
// Approx top-KC: two warps per row; per-lane top-KL (KL=5 provably covers the
// true top-5 per lane), warp merge -> sorted KC, cross-warp merge 2*KC -> KC.
// ---------------------------------------------------------------------------
__global__ __launch_bounds__(256)
void topk_kernel() {
    const int warpId = threadIdx.x >> 5;
    const int lane = threadIdx.x & 31;
    const int rloc = warpId >> 1;         // 0..3
    const int half = warpId & 1;          // 0..1
    const int row = blockIdx.x * 4 + rloc;
    const int b = row >> 11;
    const int i = row & (NI - 1);
    const float4* drow = (const float4*)(d_d2 + (size_t)b * NI * NI + (size_t)i * NI);

    __shared__ float sv[4][2 * KC];
    __shared__ int   si[4][2 * KC];

    float bd[KL]; int bix[KL];
#pragma unroll
    for (int k = 0; k < KL; k++) { bd[k] = 3.4e38f; bix[k] = 0x7fffffff; }

    const int base = half * (NI / 2);
#pragma unroll
    for (int it = 0; it < 4; it++) {
        const int j0 = base + it * 256 + lane * 8;
        float4 da = __ldcs(drow + (j0 >> 2));
        float4 db = __ldcs(drow + (j0 >> 2) + 1);
        float vs[8] = {da.x, da.y, da.z, da.w, db.x, db.y, db.z, db.w};
#pragma unroll
        for (int t = 0; t < 8; t++) {
            float v = vs[t];
            if (v < bd[KL - 1]) {
                bd[KL - 1] = v; bix[KL - 1] = j0 + t;
#pragma unroll
                for (int q = KL - 1; q > 0; q--) {
                    if (bd[q] < bd[q - 1]) {
                        float tf = bd[q]; bd[q] = bd[q - 1]; bd[q - 1] = tf;
                        int ti = bix[q]; bix[q] = bix[q - 1]; bix[q - 1] = ti;
                    }
                }
            }
        }
    }

    // per-warp merge (over 32 lanes x KL) -> sorted KC into smem
    {
        int cp = 0;
        float cv = bd[0]; int ci = bix[0];
#pragma unroll
        for (int k = 0; k < KC; k++) {
            float rv = cv; int ri = ci;
#pragma unroll
            for (int off = 16; off > 0; off >>= 1) {
                float ov = __shfl_xor_sync(0xffffffffu, rv, off);
                int   oj = __shfl_xor_sync(0xffffffffu, ri, off);
                if (ov < rv || (ov == rv && oj < ri)) { rv = ov; ri = oj; }
            }
            if (lane == 0) { sv[rloc][half * KC + k] = rv; si[rloc][half * KC + k] = ri; }
            if (cv == rv && ci == ri) {
                cp++;
                float nv = 3.4e38f; int ni2 = 0x7fffffff;
#pragma unroll
                for (int q = 1; q < KL; q++) if (cp == q) { nv = bd[q]; ni2 = bix[q]; }
                cv = nv; ci = ni2;
            }
        }
    }
    __syncthreads();

    // final merge (even warps): 2*KC candidates in lanes, KC argmin rounds
    if (half == 0) {
        float mv = 3.4e38f; int mi = 0x7fffffff;
        if (lane < 2 * KC) { mv = sv[rloc][lane]; mi = si[rloc][lane]; }
        int* oc = d_cand + (size_t)row * KC;
#pragma unroll
        for (int k = 0; k < KC; k++) {
            float rv = mv; int ri = mi;
#pragma unroll
            for (int off = 16; off > 0; off >>= 1) {
                float ov = __shfl_xor_sync(0xffffffffu, rv, off);
                int   oj = __shfl_xor_sync(0xffffffffu, ri, off);
                if (ov < rv || (ov == rv && oj < ri)) { rv = ov; ri = oj; }
            }
            if (lane == 0) oc[k] = ri;
            if (mv == rv && mi == ri) { mv = 3.4e38f; mi = 0x7fffffff; }
        }
    }
}

// ---------------------------------------------------------------------------
// Exact fp32 re-rank of KC candidates -> true top-KN.
// ---------------------------------------------------------------------------
__global__ void rerank_kernel() {
    const int row = blockIdx.x;
    const int b = row >> 11;
    const int wid = threadIdx.x >> 5, lane = threadIdx.x & 31;
    __shared__ float sval[KC];
    __shared__ int   sidx[KC];

    if (wid < KC) {
        const int j = d_cand[(size_t)row * KC + wid];
        const float* xi = d_x + (size_t)row * HD;
        const float* xj = d_x + (size_t)(b * NI + j) * HD;
        float acc = 0.f;
#pragma unroll
        for (int t = 0; t < 4; t++) {
            float4 a = *(const float4*)(xi + (lane + t * 32) * 4);
            float4 c = *(const float4*)(xj + (lane + t * 32) * 4);
            acc += a.x * c.x + a.y * c.y + a.z * c.z + a.w * c.w;
        }
#pragma unroll
        for (int o = 16; o > 0; o >>= 1) acc += __shfl_down_sync(0xffffffffu, acc, o);
        if (lane == 0) {
            sval[wid] = d_sq[b * NI + j] - 2.f * acc;
            sidx[wid] = j;
        }
    }
    __syncthreads();
    if (threadIdx.x == 0) {
        int* oi = d_idx + (size_t)row * KN;
        bool used[KC];
#pragma unroll
        for (int k = 0; k < KC; k++) used[k] = false;
#pragma unroll
        for (int k = 0; k < KN; k++) {
            float best = 3.5e38f; int bi = 0x7fffffff; int bp = 0;
#pragma unroll
            for (int t = 0; t < KC; t++) {
                if (!used[t]) {
                    float v = sval[t]; int ii = sidx[t];
                    if (v < best || (v == best && ii < bi)) { best = v; bi = ii; bp = t; }
                }
            }
            used[bp] = true;
            oi[k] = bi;
        }
    }
}

// ---------------------------------------------------------------------------
// EdgeConv: g[row,h] = max_k relu(P - Q + b_g + Q[nbr_k]) — 2 rows per block
// ---------------------------------------------------------------------------
__global__ __launch_bounds__(256)
void edgeconv_kernel(const float* __restrict__ bgv) {
    const int pr = threadIdx.x >> 7;            // 0..1
    const int row = blockIdx.x * 2 + pr;
    const int b = row >> 11;
    const int tid = threadIdx.x & 127;
    __shared__ int sj[2][KN];
    if (tid < KN) sj[pr][tid] = d_idx[(size_t)row * KN + tid];
    __syncthreads();
    const int hh = tid * 4;
    float4 p  = *(const float4*)(d_P + (size_t)row * HD + hh);
    float4 q  = *(const float4*)(d_Q + (size_t)row * HD + hh);
    float4 bg = *(const float4*)(bgv + hh);
    float bx_ = p.x - q.x + bg.x;
    float by_ = p.y - q.y + bg.y;
    float bz_ = p.z - q.z + bg.z;
    float bw_ = p.w - q.w + bg.w;
    float mx = 0.f, my = 0.f, mz = 0.f, mw = 0.f;
    const float* Qb = d_Q + (size_t)b * NI * HD;
#pragma unroll
    for (int k = 0; k < KN; k++) {
        float4 qk = *(const float4*)(Qb + (size_t)sj[pr][k] * HD + hh);
        mx = fmaxf(mx, bx_ + qk.x);
        my = fmaxf(my, by_ + qk.y);
        mz = fmaxf(mz, bz_ + qk.z);
        mw = fmaxf(mw, bw_ + qk.w);
    }
    float4 o; o.x = mx; o.y = my; o.z = mz; o.w = mw;
    *(float4*)(d_g + (size_t)row * HD + hh) = o;
}

__device__ __forceinline__ float blockReduceSum(float v, float* sh) {
    int lane = threadIdx.x & 31, w = threadIdx.x >> 5;
#pragma unroll
    for (int o = 16; o > 0; o >>= 1) v += __shfl_down_sync(0xffffffffu, v, o);
    if (lane == 0) sh[w] = v;
    __syncthreads();
    int nw = blockDim.x >> 5;
    v = (threadIdx.x < nw) ? sh[threadIdx.x] : 0.f;
    if (w == 0)
#pragma unroll
        for (int o = 16; o > 0; o >>= 1) v += __shfl_down_sync(0xffffffffu, v, o);
    return v;
}

// ---------------------------------------------------------------------------
// Gated attention score -> A_raw
// ---------------------------------------------------------------------------
__global__ void gate_kernel(const float* __restrict__ ba, const float* __restrict__ bb,
                            const float* __restrict__ Wc, const float* __restrict__ bc,
                            float* __restrict__ out) {
    const int row = blockIdx.x, tid = threadIdx.x;
    __shared__ float sh[32];
    const float* ap = d_Ap + (size_t)row * DA;
    const float* bp = d_Bp + (size_t)row * DA;
    float s = 0.f;
    for (int dd = tid; dd < DA; dd += 128) {
        float av = tanhf(ap[dd] + ba[dd]);
        float bv = bp[dd] + bb[dd];
        bv = 1.f / (1.f + expf(-bv));
        s += av * bv * Wc[dd];
    }
    s = blockReduceSum(s, sh);
    if (tid == 0) {
        float v = s + bc[0];
        d_Ar[row] = v;
        out[2 * NB * NC + row] = v;
    }
}

// ---------------------------------------------------------------------------
// Per-bag softmax stats; zero d_M.
// ---------------------------------------------------------------------------
__global__ void attn_stats_kernel() {
    const int b = blockIdx.x, tid = threadIdx.x;
    __shared__ float red[512];
    float* Ar = d_Ar + (size_t)b * NI;

    float mx = -3.4e38f;
    for (int n = tid; n < NI; n += 512) mx = fmaxf(mx, Ar[n]);
    red[tid] = mx; __syncthreads();
    for (int s = 256; s > 0; s >>= 1) { if (tid < s) red[tid] = fmaxf(red[tid], red[tid + s]); __syncthreads(); }
    mx = red[0];
    __syncthreads();

    float sum = 0.f;
    for (int n = tid; n < NI; n += 512) sum += expf(Ar[n] - mx);
    red[tid] = sum; __syncthreads();
    for (int s = 256; s > 0; s >>= 1) { if (tid < s) red[tid] += red[tid + s]; __syncthreads(); }
    const float inv = 1.f / red[0];
    __syncthreads();

    for (int n = tid; n < NI; n += 512) Ar[n] = expf(Ar[n] - mx) * inv;
    d_M[b * HD + tid] = 0.f;
}

// ---------------------------------------------------------------------------
// Chunked weighted pooling with atomics
// ---------------------------------------------------------------------------
__global__ void pool_acc_kernel() {
    const int b = blockIdx.x, ch = blockIdx.y, tid = threadIdx.x;
    const float* w  = d_Ar + (size_t)b * NI + ch * 128;
    const float* gb = d_g + ((size_t)b * NI + (size_t)ch * 128) * HD;
    __shared__ float ws[128];
    if (tid < 128) ws[tid] = w[tid];
    __syncthreads();
    const int c0 = tid, c1 = tid + 256;
    float a0 = 0.f, a1 = 0.f;
    for (int n = 0; n < 128; n++) {
        const float wn = ws[n];
        a0 = fmaf(wn, gb[(size_t)n * HD + c0], a0);
        a1 = fmaf(wn, gb[(size_t)n * HD + c1], a1);
    }
    atomicAdd(&d_M[b * HD + c0], a0);
    atomicAdd(&d_M[b * HD + c1], a1);
}

// ---------------------------------------------------------------------------
// Classifier head + Y_prob
// ---------------------------------------------------------------------------
__global__ void head_kernel(const float* __restrict__ Wcls, const float* __restrict__ bcls,
                            float* __restrict__ out) {
    const int b = blockIdx.x, tid = threadIdx.x;
    __shared__ float sh[32];
    float s0 = 0.f, s1 = 0.f;
    for (int hh = tid; hh < HD; hh += 128) {
        float m = d_M[b * HD + hh];
        s0 = fmaf(m, Wcls[hh * NC + 0], s0);
        s1 = fmaf(m, Wcls[hh * NC + 1], s1);
    }
    s0 = blockReduceSum(s0, sh);
    __syncthreads();
    s1 = blockReduceSum(s1, sh);
    if (tid == 0) {
        float l0 = s0 + bcls[0], l1 = s1 + bcls[1];
        out[b * NC + 0] = l0;
        out[b * NC + 1] = l1;
        float mx = fmaxf(l0, l1);
        float e0 = expf(l0 - mx), e1 = expf(l1 - mx);
        float inv = 1.f / (e0 + e1);
        out[NB * NC + b * NC + 0] = e0 * inv;
        out[NB * NC + b * NC + 1] = e1 * inv;
    }
}

// ---------------------------------------------------------------------------
extern "C" void kernel_launch(void* const* d_in, const int* in_sizes, int n_in,
                              void* d_out, int out_size) {
    const float* h     = (const float*)d_in[0];
    const float* W_fc  = (const float*)d_in[1];
    const float* b_fc  = (const float*)d_in[2];
    const float* W_g   = (const float*)d_in[3];
    const float* b_g   = (const float*)d_in[4];
    const float* W_a   = (const float*)d_in[5];
    const float* b_a   = (const float*)d_in[6];
    const float* W_b   = (const float*)d_in[7];
    const float* b_b   = (const float*)d_in[8];
    const float* W_c   = (const float*)d_in[9];
    const float* b_c   = (const float*)d_in[10];
    const float* W_cls = (const float*)d_in[11];
    const float* b_cls = (const float*)d_in[12];
    float* out = (float*)d_out;

    static cudaStream_t s2 = nullptr;
    static cudaEvent_t evFork = nullptr, evJoin = nullptr;
    static bool inited = false;
    if (!inited) {
        if (cudaStreamCreateWithFlags(&s2, cudaStreamNonBlocking) != cudaSuccess) s2 = nullptr;
        if (s2) {
            if (cudaEventCreateWithFlags(&evFork, cudaEventDisableTiming) != cudaSuccess ||
                cudaEventCreateWithFlags(&evJoin, cudaEventDisableTiming) != cudaSuccess) {
                s2 = nullptr;
            }
        }
        inited = true;
    }

    void *px, *pP, *pQ, *pg, *pAp, *pBp, *pd2, *psq;
    cudaGetSymbolAddress(&px, d_x);
    cudaGetSymbolAddress(&pP, d_P);
    cudaGetSymbolAddress(&pQ, d_Q);
    cudaGetSymbolAddress(&pg, d_g);
    cudaGetSymbolAddress(&pAp, d_Ap);
    cudaGetSymbolAddress(&pBp, d_Bp);
    cudaGetSymbolAddress(&pd2, d_d2);
    cudaGetSymbolAddress(&psq, d_sq);
    float* x  = (float*)px;
    float* P  = (float*)pP;
    float* Q  = (float*)pQ;
    float* g  = (float*)pg;
    float* Ap = (float*)pAp;
    float* Bp = (float*)pBp;
    float* d2 = (float*)pd2;

    const int NT = NI / XBN;   // 16

    // 0. zero d_sq (fused-sqnorm accumulator)
    cudaMemsetAsync(psq, 0, MROWS * sizeof(float), 0);
    // 1. x = relu(h @ W_fc + b_fc)  — fp32 FFMA exact, fused row sqnorm
    gemm_f32_relu<<<dim3(HD / FBN, MROWS / FBM), 256>>>(h, W_fc, b_fc, x, MROWS, DIM, HD);

    if (s2) {
        // fork: side stream runs Gram -> topk -> rerank
        cudaEventRecord(evFork, 0);
        cudaStreamWaitEvent(s2, evFork, 0);
        gemm_bf<2, 1><<<dim3(NT, NT, NB), 256, 0, s2>>>(x, nullptr, nullptr, d2, nullptr, NI, HD, NI);
        topk_kernel<<<MROWS / 4, 256, 0, s2>>>();
        rerank_kernel<<<MROWS, KC * 32, 0, s2>>>();
        cudaEventRecord(evJoin, s2);
        // main stream: P and Q (fused z-launch) in parallel
        gemm_bf<0, 0><<<dim3(HD / XBN, MROWS / XBM, 2), 256>>>(
            x, W_g, W_g + (size_t)HD * HD, P, Q, MROWS, HD, HD);
        cudaStreamWaitEvent(0, evJoin, 0);
    } else {
        gemm_bf<2, 1><<<dim3(NT, NT, NB), 256>>>(x, nullptr, nullptr, d2, nullptr, NI, HD, NI);
        topk_kernel<<<MROWS / 4, 256>>>();
        rerank_kernel<<<MROWS, KC * 32>>>();
        gemm_bf<0, 0><<<dim3(HD / XBN, MROWS / XBM, 2), 256>>>(
            x, W_g, W_g + (size_t)HD * HD, P, Q, MROWS, HD, HD);
    }

    // 7. edgeconv gather + max (2 rows/block)
    edgeconv_kernel<<<MROWS / 2, 256>>>(b_g);
    // 8/9. attention pre-projections (fused z-launch; biases in gate)
    gemm_bf<0, 0><<<dim3(DA / XBN, MROWS / XBM, 2), 256>>>(
        g, W_a, W_b, Ap, Bp, MROWS, HD, DA);
    // 10. gated attention score -> A_raw
    gate_kernel<<<MROWS, 128>>>(b_a, b_b, W_c, b_c, out);
    // 11. softmax stats + zero M
    attn_stats_kernel<<<NB, 512>>>();
    // 12. chunked weighted pooling
    pool_acc_kernel<<<dim3(NB, 16), 256>>>();
    // 13. classifier head + Y_prob
    head_kernel<<<NB, 128>>>(W_cls, b_cls, out);
}